// round 1
// baseline (speedup 1.0000x reference)
#include <cuda_runtime.h>
#include <math.h>

#define BB 2
#define SS 2048
#define DD 1024
#define HH 16
#define DHD 64
#define DFF 4096
#define NROWS (BB * SS)

// ---------------- scratch (device globals; no allocation) ----------------
__device__ float g_ln[NROWS * DD];
__device__ float g_q[NROWS * DD];
__device__ float g_k[NROWS * DD];
__device__ float g_v[NROWS * DD];
__device__ float g_attn[NROWS * DD];
__device__ float g_h1[NROWS * DD];
__device__ float g_f1[NROWS * DFF];

// ---------------- LayerNorm (faithful: Bessel var, eps added to std) -----
__global__ void __launch_bounds__(256) ln_kernel(
    const float* __restrict__ x, const float* __restrict__ gw,
    const float* __restrict__ bw, float* __restrict__ y)
{
    int row = blockIdx.x;
    int t = threadIdx.x;
    const float4* xr = (const float4*)(x + (size_t)row * DD);
    float4 v = xr[t];
    float s  = v.x + v.y + v.z + v.w;
    float ss = v.x * v.x + v.y * v.y + v.z * v.z + v.w * v.w;

    __shared__ float rs[8], rss[8];
    #pragma unroll
    for (int o = 16; o; o >>= 1) {
        s  += __shfl_xor_sync(0xffffffffu, s,  o);
        ss += __shfl_xor_sync(0xffffffffu, ss, o);
    }
    if ((t & 31) == 0) { rs[t >> 5] = s; rss[t >> 5] = ss; }
    __syncthreads();
    __shared__ float mean_s, rd_s;
    if (t == 0) {
        float S = 0.f, SQ = 0.f;
        #pragma unroll
        for (int i = 0; i < 8; i++) { S += rs[i]; SQ += rss[i]; }
        float mean = S * (1.0f / DD);
        float var  = (SQ - S * S * (1.0f / DD)) * (1.0f / (DD - 1));
        var = fmaxf(var, 0.f);
        mean_s = mean;
        rd_s = 1.0f / (sqrtf(var) + 1e-6f);
    }
    __syncthreads();
    float mean = mean_s, rd = rd_s;
    float4 g4 = ((const float4*)gw)[t];
    float4 b4 = ((const float4*)bw)[t];
    float4 o;
    o.x = g4.x * (v.x - mean) * rd + b4.x;
    o.y = g4.y * (v.y - mean) * rd + b4.y;
    o.z = g4.z * (v.z - mean) * rd + b4.z;
    o.w = g4.w * (v.w - mean) * rd + b4.w;
    ((float4*)(y + (size_t)row * DD))[t] = o;
}

// ---------------- SGEMM 128x128x8, 8x8/thread, fused epilogue -------------
// EPI: 0 = bias, 1 = bias + tanh-GELU, 2 = bias + residual add
__device__ __forceinline__ float gelu_tanh_f(float h) {
    const float c = 0.7978845608028654f;
    float u = c * (h + 0.044715f * h * h * h);
    return 0.5f * h * (1.0f + tanhf(u));
}

template <int EPI>
__global__ void __launch_bounds__(256) sgemm_kernel(
    const float* __restrict__ A, const float* __restrict__ W,
    const float* __restrict__ bias, const float* __restrict__ R,
    float* __restrict__ C, int M, int K, int N)
{
    __shared__ float As[8][128];
    __shared__ float Bs[8][128];
    int t = threadIdx.x;
    int tx = t & 15, ty = t >> 4;
    int m0 = blockIdx.y * 128, n0 = blockIdx.x * 128;

    float acc[8][8];
    #pragma unroll
    for (int i = 0; i < 8; i++)
        #pragma unroll
        for (int j = 0; j < 8; j++) acc[i][j] = 0.f;

    int ar = t >> 1, ac = (t & 1) * 4;
    int br = t >> 5, bc = (t & 31) * 4;
    const float* Aptr = A + (size_t)(m0 + ar) * K + ac;
    const float* Wptr = W + (size_t)br * N + n0 + bc;

    for (int k0 = 0; k0 < K; k0 += 8) {
        float4 av = *(const float4*)(Aptr + k0);
        float4 bv = *(const float4*)(Wptr + (size_t)k0 * N);
        __syncthreads();
        As[ac + 0][ar] = av.x;
        As[ac + 1][ar] = av.y;
        As[ac + 2][ar] = av.z;
        As[ac + 3][ar] = av.w;
        *(float4*)&Bs[br][bc] = bv;
        __syncthreads();
        #pragma unroll
        for (int k = 0; k < 8; k++) {
            float a[8], b[8];
            *(float4*)(a)     = *(float4*)&As[k][ty * 8];
            *(float4*)(a + 4) = *(float4*)&As[k][ty * 8 + 4];
            *(float4*)(b)     = *(float4*)&Bs[k][tx * 8];
            *(float4*)(b + 4) = *(float4*)&Bs[k][tx * 8 + 4];
            #pragma unroll
            for (int i = 0; i < 8; i++)
                #pragma unroll
                for (int j = 0; j < 8; j++)
                    acc[i][j] += a[i] * b[j];
        }
    }

    int tn = n0 + tx * 8;
    float4 bia0 = *(const float4*)(bias + tn);
    float4 bia1 = *(const float4*)(bias + tn + 4);
    float biav[8] = {bia0.x, bia0.y, bia0.z, bia0.w, bia1.x, bia1.y, bia1.z, bia1.w};

    #pragma unroll
    for (int i = 0; i < 8; i++) {
        int m = m0 + ty * 8 + i;
        float cv[8];
        #pragma unroll
        for (int j = 0; j < 8; j++) cv[j] = acc[i][j] + biav[j];
        if (EPI == 1) {
            #pragma unroll
            for (int j = 0; j < 8; j++) cv[j] = gelu_tanh_f(cv[j]);
        }
        if (EPI == 2) {
            float4 r0 = *(const float4*)(R + (size_t)m * N + tn);
            float4 r1 = *(const float4*)(R + (size_t)m * N + tn + 4);
            cv[0] += r0.x; cv[1] += r0.y; cv[2] += r0.z; cv[3] += r0.w;
            cv[4] += r1.x; cv[5] += r1.y; cv[6] += r1.z; cv[7] += r1.w;
        }
        *(float4*)(C + (size_t)m * N + tn)     = make_float4(cv[0], cv[1], cv[2], cv[3]);
        *(float4*)(C + (size_t)m * N + tn + 4) = make_float4(cv[4], cv[5], cv[6], cv[7]);
    }
}

// ---------------- Flash attention (fp32, 64x64 tiles) ---------------------
#define FLASH_SMEM ((64 * 64 + 64 * 68 + 64 * 64 + 64 * 64 + 64) * 4)

__global__ void __launch_bounds__(256) flash_kernel(
    const float* __restrict__ Q, const float* __restrict__ Kg,
    const float* __restrict__ Vg, const int* __restrict__ mask,
    float* __restrict__ O)
{
    extern __shared__ float sm[];
    float* Qs  = sm;                   // [64][64]
    float* KsT = Qs + 64 * 64;         // [64][68] transposed: KsT[d][j]
    float* Vs  = KsT + 64 * 68;        // [64][64]
    float* Ps  = Vs + 64 * 64;         // [64][64]
    float* mb  = Ps + 64 * 64;         // [64]

    int t = threadIdx.x;
    int tx = t & 15, ty = t >> 4;
    int q0 = blockIdx.x * 64;
    int h  = blockIdx.y;
    int b  = blockIdx.z;
    size_t baseQ = ((size_t)(b * SS + q0)) * DD + h * DHD;

    #pragma unroll 4
    for (int p = t; p < 1024; p += 256) {
        int row = p >> 4, c4 = (p & 15) << 2;
        *(float4*)&Qs[row * 64 + c4] =
            *(const float4*)(Q + baseQ + (size_t)row * DD + c4);
    }

    float mrow[4], lrow[4], acc[4][4];
    #pragma unroll
    for (int r = 0; r < 4; r++) {
        mrow[r] = -1e30f; lrow[r] = 0.f;
        #pragma unroll
        for (int c = 0; c < 4; c++) acc[r][c] = 0.f;
    }
    const float scale = 0.125f; // 1/sqrt(64)

    for (int k0 = 0; k0 < SS; k0 += 64) {
        __syncthreads();
        size_t baseK = ((size_t)(b * SS + k0)) * DD + h * DHD;
        #pragma unroll 4
        for (int p = t; p < 1024; p += 256) {
            int row = p >> 4, c4 = (p & 15) << 2;
            float4 kv = *(const float4*)(Kg + baseK + (size_t)row * DD + c4);
            KsT[(c4 + 0) * 68 + row] = kv.x;
            KsT[(c4 + 1) * 68 + row] = kv.y;
            KsT[(c4 + 2) * 68 + row] = kv.z;
            KsT[(c4 + 3) * 68 + row] = kv.w;
            *(float4*)&Vs[row * 64 + c4] =
                *(const float4*)(Vg + baseK + (size_t)row * DD + c4);
        }
        if (t < 64) mb[t] = (mask[b * SS + k0 + t] == 0) ? -1e9f : 0.f;
        __syncthreads();

        float s[4][4];
        #pragma unroll
        for (int r = 0; r < 4; r++)
            #pragma unroll
            for (int c = 0; c < 4; c++) s[r][c] = 0.f;

        #pragma unroll 8
        for (int d = 0; d < 64; d++) {
            float a[4];
            #pragma unroll
            for (int r = 0; r < 4; r++) a[r] = Qs[(ty * 4 + r) * 64 + d];
            float4 kv4 = *(const float4*)&KsT[d * 68 + tx * 4];
            #pragma unroll
            for (int r = 0; r < 4; r++) {
                s[r][0] += a[r] * kv4.x;
                s[r][1] += a[r] * kv4.y;
                s[r][2] += a[r] * kv4.z;
                s[r][3] += a[r] * kv4.w;
            }
        }

        float mbv[4];
        #pragma unroll
        for (int c = 0; c < 4; c++) mbv[c] = mb[tx * 4 + c];

        float mloc[4];
        #pragma unroll
        for (int r = 0; r < 4; r++) {
            mloc[r] = -1e30f;
            #pragma unroll
            for (int c = 0; c < 4; c++) {
                s[r][c] = s[r][c] * scale + mbv[c];
                mloc[r] = fmaxf(mloc[r], s[r][c]);
            }
        }
        #pragma unroll
        for (int o = 8; o; o >>= 1)
            #pragma unroll
            for (int r = 0; r < 4; r++)
                mloc[r] = fmaxf(mloc[r], __shfl_xor_sync(0xffffffffu, mloc[r], o));

        float alpha[4], lloc[4];
        #pragma unroll
        for (int r = 0; r < 4; r++) {
            float mn = fmaxf(mrow[r], mloc[r]);
            alpha[r] = expf(mrow[r] - mn);
            mrow[r] = mn;
            float ls = 0.f;
            #pragma unroll
            for (int c = 0; c < 4; c++) {
                float pv = expf(s[r][c] - mn);
                s[r][c] = pv;
                ls += pv;
            }
            lloc[r] = ls;
        }
        #pragma unroll
        for (int o = 8; o; o >>= 1)
            #pragma unroll
            for (int r = 0; r < 4; r++)
                lloc[r] += __shfl_xor_sync(0xffffffffu, lloc[r], o);

        #pragma unroll
        for (int r = 0; r < 4; r++) {
            lrow[r] = lrow[r] * alpha[r] + lloc[r];
            #pragma unroll
            for (int c = 0; c < 4; c++) acc[r][c] *= alpha[r];
            *(float4*)&Ps[(ty * 4 + r) * 64 + tx * 4] =
                make_float4(s[r][0], s[r][1], s[r][2], s[r][3]);
        }
        __syncthreads();

        #pragma unroll 8
        for (int j = 0; j < 64; j++) {
            float4 vv = *(const float4*)&Vs[j * 64 + tx * 4];
            #pragma unroll
            for (int r = 0; r < 4; r++) {
                float pv = Ps[(ty * 4 + r) * 64 + j];
                acc[r][0] += pv * vv.x;
                acc[r][1] += pv * vv.y;
                acc[r][2] += pv * vv.z;
                acc[r][3] += pv * vv.w;
            }
        }
    }

    #pragma unroll
    for (int r = 0; r < 4; r++) {
        float inv = 1.f / lrow[r];
        *(float4*)(O + baseQ + (size_t)(ty * 4 + r) * DD + tx * 4) =
            make_float4(acc[r][0] * inv, acc[r][1] * inv,
                        acc[r][2] * inv, acc[r][3] * inv);
    }
}

// ---------------- launch ---------------------------------------------------
extern "C" void kernel_launch(void* const* d_in, const int* in_sizes, int n_in,
                              void* d_out, int out_size)
{
    const float* hidden = (const float*)d_in[0];
    const int*   mask   = (const int*)d_in[1];
    const float* wq = (const float*)d_in[2];
    const float* bq = (const float*)d_in[3];
    const float* wk = (const float*)d_in[4];
    const float* bk = (const float*)d_in[5];
    const float* wv = (const float*)d_in[6];
    const float* bv = (const float*)d_in[7];
    const float* wo = (const float*)d_in[8];
    const float* bo = (const float*)d_in[9];
    const float* w1 = (const float*)d_in[10];
    const float* b1 = (const float*)d_in[11];
    const float* w2 = (const float*)d_in[12];
    const float* b2 = (const float*)d_in[13];
    const float* ln1_g = (const float*)d_in[14];
    const float* ln1_b = (const float*)d_in[15];
    const float* ln2_g = (const float*)d_in[16];
    const float* ln2_b = (const float*)d_in[17];
    float* out = (float*)d_out;

    float *ln, *q, *k, *v, *attn, *h1, *f1;
    cudaGetSymbolAddress((void**)&ln,   g_ln);
    cudaGetSymbolAddress((void**)&q,    g_q);
    cudaGetSymbolAddress((void**)&k,    g_k);
    cudaGetSymbolAddress((void**)&v,    g_v);
    cudaGetSymbolAddress((void**)&attn, g_attn);
    cudaGetSymbolAddress((void**)&h1,   g_h1);
    cudaGetSymbolAddress((void**)&f1,   g_f1);

    cudaFuncSetAttribute(flash_kernel,
                         cudaFuncAttributeMaxDynamicSharedMemorySize, FLASH_SMEM);

    // 1) LN1
    ln_kernel<<<NROWS, 256>>>(hidden, ln1_g, ln1_b, ln);

    // 2) Q, K, V projections
    dim3 gD(DD / 128, NROWS / 128);
    sgemm_kernel<0><<<gD, 256>>>(ln, wq, bq, nullptr, q, NROWS, DD, DD);
    sgemm_kernel<0><<<gD, 256>>>(ln, wk, bk, nullptr, k, NROWS, DD, DD);
    sgemm_kernel<0><<<gD, 256>>>(ln, wv, bv, nullptr, v, NROWS, DD, DD);

    // 3) attention
    flash_kernel<<<dim3(SS / 64, HH, BB), 256, FLASH_SMEM>>>(q, k, v, mask, attn);

    // 4) output projection + residual
    sgemm_kernel<2><<<gD, 256>>>(attn, wo, bo, hidden, h1, NROWS, DD, DD);

    // 5) LN2
    ln_kernel<<<NROWS, 256>>>(h1, ln2_g, ln2_b, ln);

    // 6) FFN
    dim3 gF(DFF / 128, NROWS / 128);
    sgemm_kernel<1><<<gF, 256>>>(ln, w1, b1, nullptr, f1, NROWS, DD, DFF);
    sgemm_kernel<2><<<gD, 256>>>(f1, w2, b2, h1, out, NROWS, DFF, DD);
}

// round 3
// speedup vs baseline: 2.0128x; 2.0128x over previous
#include <cuda_runtime.h>
#include <math.h>
#include <stdint.h>

#define BB 2
#define SS 2048
#define DD 1024
#define HH 16
#define DHD 64
#define DFF 4096
#define NROWS (BB * SS)

// ---------------- scratch (device globals; no allocation) ----------------
__device__ float g_ln[NROWS * DD];
__device__ float g_q[NROWS * DD];
__device__ float g_k[NROWS * DD];
__device__ float g_v[NROWS * DD];
__device__ float g_attn[NROWS * DD];
__device__ float g_h1[NROWS * DD];
__device__ float g_f1[NROWS * DFF];

// ---------------- LayerNorm (faithful: Bessel var, eps added to std) -----
__global__ void __launch_bounds__(256) ln_kernel(
    const float* __restrict__ x, const float* __restrict__ gw,
    const float* __restrict__ bw, float* __restrict__ y)
{
    int row = blockIdx.x;
    int t = threadIdx.x;
    const float4* xr = (const float4*)(x + (size_t)row * DD);
    float4 v = xr[t];
    float s  = v.x + v.y + v.z + v.w;
    float ss = v.x * v.x + v.y * v.y + v.z * v.z + v.w * v.w;

    __shared__ float rs[8], rss[8];
    #pragma unroll
    for (int o = 16; o; o >>= 1) {
        s  += __shfl_xor_sync(0xffffffffu, s,  o);
        ss += __shfl_xor_sync(0xffffffffu, ss, o);
    }
    if ((t & 31) == 0) { rs[t >> 5] = s; rss[t >> 5] = ss; }
    __syncthreads();
    __shared__ float mean_s, rd_s;
    if (t == 0) {
        float S = 0.f, SQ = 0.f;
        #pragma unroll
        for (int i = 0; i < 8; i++) { S += rs[i]; SQ += rss[i]; }
        float mean = S * (1.0f / DD);
        float var  = (SQ - S * S * (1.0f / DD)) * (1.0f / (DD - 1));
        var = fmaxf(var, 0.f);
        mean_s = mean;
        rd_s = 1.0f / (sqrtf(var) + 1e-6f);
    }
    __syncthreads();
    float mean = mean_s, rd = rd_s;
    float4 g4 = ((const float4*)gw)[t];
    float4 b4 = ((const float4*)bw)[t];
    float4 o;
    o.x = g4.x * (v.x - mean) * rd + b4.x;
    o.y = g4.y * (v.y - mean) * rd + b4.y;
    o.z = g4.z * (v.z - mean) * rd + b4.z;
    o.w = g4.w * (v.w - mean) * rd + b4.w;
    ((float4*)(y + (size_t)row * DD))[t] = o;
}

// ---------------- tf32 mma.sync GEMM --------------------------------------
// CTA tile 128x128x32, 8 warps (2M x 4N), warp tile 64x32.
// A smem [128][36] (row-major, padded), B smem [32][136] (k-major, padded).
#define TK 32
#define ASTR 36
#define BSTR 136
#define A_TILE_F (128 * ASTR)          // 4608 floats
#define B_TILE_F (TK * BSTR)           // 4352 floats
#define STAGE_F (A_TILE_F + B_TILE_F)  // 8960 floats
#define NSTG 3
#define GEMM_SMEM (NSTG * STAGE_F * 4) // 107520 bytes

__device__ __forceinline__ void cp16(void* dst_smem, const void* src) {
    uint32_t d;
    asm("{ .reg .u64 t; cvta.to.shared.u64 t, %1; cvt.u32.u64 %0, t; }"
        : "=r"(d) : "l"(dst_smem));
    asm volatile("cp.async.cg.shared.global [%0], [%1], 16;" :: "r"(d), "l"(src));
}
__device__ __forceinline__ void cp_commit() {
    asm volatile("cp.async.commit_group;");
}
template <int N>
__device__ __forceinline__ void cp_wait() {
    asm volatile("cp.async.wait_group %0;" :: "n"(N));
}

__device__ __forceinline__ void mma8(float c[4], const uint32_t a[4], const uint32_t b[2]) {
    asm volatile(
        "mma.sync.aligned.m16n8k8.row.col.f32.tf32.tf32.f32 "
        "{%0,%1,%2,%3}, {%4,%5,%6,%7}, {%8,%9}, {%0,%1,%2,%3};"
        : "+f"(c[0]), "+f"(c[1]), "+f"(c[2]), "+f"(c[3])
        : "r"(a[0]), "r"(a[1]), "r"(a[2]), "r"(a[3]), "r"(b[0]), "r"(b[1]));
}

__device__ __forceinline__ float gelu_tanh_f(float h) {
    const float c = 0.7978845608028654f;
    float u = c * (h + 0.044715f * h * h * h);
    return 0.5f * h * (1.0f + tanhf(u));
}

// EPI: 0 = bias, 1 = bias + tanh-GELU, 2 = bias + residual add
template <int EPI>
__global__ void __launch_bounds__(256) gemm_tf32(
    const float* __restrict__ A, const float* __restrict__ W,
    const float* __restrict__ bias, const float* __restrict__ R,
    float* __restrict__ C, int M, int K, int N)
{
    extern __shared__ float sm[];
    int t = threadIdx.x;
    int m0 = blockIdx.y * 128, n0 = blockIdx.x * 128;
    int nkt = K >> 5;

    // ---- tile loader (cp.async): 4 A chunks + 4 B chunks per thread ----
    auto load_tile = [&](int stg, int kt) {
        float* As = sm + stg * STAGE_F;
        float* Bs = As + A_TILE_F;
        int k0 = kt * TK;
        #pragma unroll
        for (int i = 0; i < 4; i++) {
            int id = t + i * 256;               // 0..1023
            int row = id >> 3, c4 = (id & 7) << 2;
            cp16(As + row * ASTR + c4, A + (size_t)(m0 + row) * K + k0 + c4);
        }
        #pragma unroll
        for (int i = 0; i < 4; i++) {
            int id = t + i * 256;
            int row = id >> 5, c4 = (id & 31) << 2;
            cp16(Bs + row * BSTR + c4, W + (size_t)(k0 + row) * N + n0 + c4);
        }
    };

    float acc[4][4][4];
    #pragma unroll
    for (int mt = 0; mt < 4; mt++)
        #pragma unroll
        for (int nt = 0; nt < 4; nt++)
            #pragma unroll
            for (int i = 0; i < 4; i++) acc[mt][nt][i] = 0.f;

    int lane = t & 31, wid = t >> 5;
    int warpM = wid >> 2, warpN = wid & 3;
    int g = lane >> 2, c = lane & 3;
    int arow = warpM * 64 + g;   // + mt*16 (+8 for a1/a3)
    int bcol = warpN * 32 + g;   // + nt*8

    // prologue
    #pragma unroll
    for (int s = 0; s < NSTG; s++) { load_tile(s, s); cp_commit(); }

    for (int kt = 0; kt < nkt; kt++) {
        cp_wait<NSTG - 1>();
        __syncthreads();

        const float* As = sm + (kt % NSTG) * STAGE_F;
        const float* Bs = As + A_TILE_F;

        #pragma unroll
        for (int ks = 0; ks < 4; ks++) {
            int k0 = ks * 8;
            uint32_t af[4][4], bf[4][2];
            #pragma unroll
            for (int mt = 0; mt < 4; mt++) {
                const float* ap = As + (size_t)(arow + mt * 16) * ASTR + k0 + c;
                af[mt][0] = __float_as_uint(ap[0]);
                af[mt][1] = __float_as_uint(ap[8 * ASTR]);
                af[mt][2] = __float_as_uint(ap[4]);
                af[mt][3] = __float_as_uint(ap[8 * ASTR + 4]);
            }
            #pragma unroll
            for (int nt = 0; nt < 4; nt++) {
                const float* bp = Bs + (size_t)(k0 + c) * BSTR + bcol + nt * 8;
                bf[nt][0] = __float_as_uint(bp[0]);
                bf[nt][1] = __float_as_uint(bp[4 * BSTR]);
            }
            #pragma unroll
            for (int mt = 0; mt < 4; mt++)
                #pragma unroll
                for (int nt = 0; nt < 4; nt++)
                    mma8(acc[mt][nt], af[mt], bf[nt]);
        }

        __syncthreads();
        int nx = kt + NSTG;
        if (nx < nkt) load_tile(kt % NSTG, nx);
        cp_commit();   // empty group in tail keeps wait arithmetic in order
    }

    // ---- epilogue ----
    int rbase = m0 + warpM * 64 + g;
    int cbase = n0 + warpN * 32 + 2 * c;

    #pragma unroll
    for (int nt = 0; nt < 4; nt++) {
        int col = cbase + nt * 8;
        float2 b2 = *(const float2*)(bias + col);
        #pragma unroll
        for (int mt = 0; mt < 4; mt++) {
            int r0 = rbase + mt * 16;
            float v0x = acc[mt][nt][0] + b2.x;
            float v0y = acc[mt][nt][1] + b2.y;
            float v1x = acc[mt][nt][2] + b2.x;
            float v1y = acc[mt][nt][3] + b2.y;
            if (EPI == 1) {
                v0x = gelu_tanh_f(v0x); v0y = gelu_tanh_f(v0y);
                v1x = gelu_tanh_f(v1x); v1y = gelu_tanh_f(v1y);
            }
            if (EPI == 2) {
                float2 r0v = *(const float2*)(R + (size_t)r0 * N + col);
                float2 r1v = *(const float2*)(R + (size_t)(r0 + 8) * N + col);
                v0x += r0v.x; v0y += r0v.y; v1x += r1v.x; v1y += r1v.y;
            }
            *(float2*)(C + (size_t)r0 * N + col)       = make_float2(v0x, v0y);
            *(float2*)(C + (size_t)(r0 + 8) * N + col) = make_float2(v1x, v1y);
        }
    }
}

// ---------------- Flash attention (fp32, 64x64 tiles) ---------------------
#define FLASH_SMEM ((64 * 64 + 64 * 68 + 64 * 64 + 64 * 64 + 64) * 4)

__global__ void __launch_bounds__(256) flash_kernel(
    const float* __restrict__ Q, const float* __restrict__ Kg,
    const float* __restrict__ Vg, const int* __restrict__ mask,
    float* __restrict__ O)
{
    extern __shared__ float sm[];
    float* Qs  = sm;
    float* KsT = Qs + 64 * 64;
    float* Vs  = KsT + 64 * 68;
    float* Ps  = Vs + 64 * 64;
    float* mb  = Ps + 64 * 64;

    int t = threadIdx.x;
    int tx = t & 15, ty = t >> 4;
    int q0 = blockIdx.x * 64;
    int h  = blockIdx.y;
    int b  = blockIdx.z;
    size_t baseQ = ((size_t)(b * SS + q0)) * DD + h * DHD;

    #pragma unroll 4
    for (int p = t; p < 1024; p += 256) {
        int row = p >> 4, c4 = (p & 15) << 2;
        *(float4*)&Qs[row * 64 + c4] =
            *(const float4*)(Q + baseQ + (size_t)row * DD + c4);
    }

    float mrow[4], lrow[4], acc[4][4];
    #pragma unroll
    for (int r = 0; r < 4; r++) {
        mrow[r] = -1e30f; lrow[r] = 0.f;
        #pragma unroll
        for (int c = 0; c < 4; c++) acc[r][c] = 0.f;
    }
    const float scale = 0.125f;

    for (int k0 = 0; k0 < SS; k0 += 64) {
        __syncthreads();
        size_t baseK = ((size_t)(b * SS + k0)) * DD + h * DHD;
        #pragma unroll 4
        for (int p = t; p < 1024; p += 256) {
            int row = p >> 4, c4 = (p & 15) << 2;
            float4 kv = *(const float4*)(Kg + baseK + (size_t)row * DD + c4);
            KsT[(c4 + 0) * 68 + row] = kv.x;
            KsT[(c4 + 1) * 68 + row] = kv.y;
            KsT[(c4 + 2) * 68 + row] = kv.z;
            KsT[(c4 + 3) * 68 + row] = kv.w;
            *(float4*)&Vs[row * 64 + c4] =
                *(const float4*)(Vg + baseK + (size_t)row * DD + c4);
        }
        if (t < 64) mb[t] = (mask[b * SS + k0 + t] == 0) ? -1e9f : 0.f;
        __syncthreads();

        float s[4][4];
        #pragma unroll
        for (int r = 0; r < 4; r++)
            #pragma unroll
            for (int c = 0; c < 4; c++) s[r][c] = 0.f;

        #pragma unroll 8
        for (int d = 0; d < 64; d++) {
            float a[4];
            #pragma unroll
            for (int r = 0; r < 4; r++) a[r] = Qs[(ty * 4 + r) * 64 + d];
            float4 kv4 = *(const float4*)&KsT[d * 68 + tx * 4];
            #pragma unroll
            for (int r = 0; r < 4; r++) {
                s[r][0] += a[r] * kv4.x;
                s[r][1] += a[r] * kv4.y;
                s[r][2] += a[r] * kv4.z;
                s[r][3] += a[r] * kv4.w;
            }
        }

        float mbv[4];
        #pragma unroll
        for (int c = 0; c < 4; c++) mbv[c] = mb[tx * 4 + c];

        float mloc[4];
        #pragma unroll
        for (int r = 0; r < 4; r++) {
            mloc[r] = -1e30f;
            #pragma unroll
            for (int c = 0; c < 4; c++) {
                s[r][c] = s[r][c] * scale + mbv[c];
                mloc[r] = fmaxf(mloc[r], s[r][c]);
            }
        }
        #pragma unroll
        for (int o = 8; o; o >>= 1)
            #pragma unroll
            for (int r = 0; r < 4; r++)
                mloc[r] = fmaxf(mloc[r], __shfl_xor_sync(0xffffffffu, mloc[r], o));

        float alpha[4], lloc[4];
        #pragma unroll
        for (int r = 0; r < 4; r++) {
            float mn = fmaxf(mrow[r], mloc[r]);
            alpha[r] = expf(mrow[r] - mn);
            mrow[r] = mn;
            float ls = 0.f;
            #pragma unroll
            for (int c = 0; c < 4; c++) {
                float pv = expf(s[r][c] - mn);
                s[r][c] = pv;
                ls += pv;
            }
            lloc[r] = ls;
        }
        #pragma unroll
        for (int o = 8; o; o >>= 1)
            #pragma unroll
            for (int r = 0; r < 4; r++)
                lloc[r] += __shfl_xor_sync(0xffffffffu, lloc[r], o);

        #pragma unroll
        for (int r = 0; r < 4; r++) {
            lrow[r] = lrow[r] * alpha[r] + lloc[r];
            #pragma unroll
            for (int c = 0; c < 4; c++) acc[r][c] *= alpha[r];
            *(float4*)&Ps[(ty * 4 + r) * 64 + tx * 4] =
                make_float4(s[r][0], s[r][1], s[r][2], s[r][3]);
        }
        __syncthreads();

        #pragma unroll 8
        for (int j = 0; j < 64; j++) {
            float4 vv = *(const float4*)&Vs[j * 64 + tx * 4];
            #pragma unroll
            for (int r = 0; r < 4; r++) {
                float pv = Ps[(ty * 4 + r) * 64 + j];
                acc[r][0] += pv * vv.x;
                acc[r][1] += pv * vv.y;
                acc[r][2] += pv * vv.z;
                acc[r][3] += pv * vv.w;
            }
        }
    }

    #pragma unroll
    for (int r = 0; r < 4; r++) {
        float inv = 1.f / lrow[r];
        *(float4*)(O + baseQ + (size_t)(ty * 4 + r) * DD + tx * 4) =
            make_float4(acc[r][0] * inv, acc[r][1] * inv,
                        acc[r][2] * inv, acc[r][3] * inv);
    }
}

// ---------------- launch ---------------------------------------------------
extern "C" void kernel_launch(void* const* d_in, const int* in_sizes, int n_in,
                              void* d_out, int out_size)
{
    const float* hidden = (const float*)d_in[0];
    const int*   mask   = (const int*)d_in[1];
    const float* wq = (const float*)d_in[2];
    const float* bq = (const float*)d_in[3];
    const float* wk = (const float*)d_in[4];
    const float* bk = (const float*)d_in[5];
    const float* wv = (const float*)d_in[6];
    const float* bv = (const float*)d_in[7];
    const float* wo = (const float*)d_in[8];
    const float* bo = (const float*)d_in[9];
    const float* w1 = (const float*)d_in[10];
    const float* b1 = (const float*)d_in[11];
    const float* w2 = (const float*)d_in[12];
    const float* b2 = (const float*)d_in[13];
    const float* ln1_g = (const float*)d_in[14];
    const float* ln1_b = (const float*)d_in[15];
    const float* ln2_g = (const float*)d_in[16];
    const float* ln2_b = (const float*)d_in[17];
    float* out = (float*)d_out;

    float *ln, *q, *k, *v, *attn, *h1, *f1;
    cudaGetSymbolAddress((void**)&ln,   g_ln);
    cudaGetSymbolAddress((void**)&q,    g_q);
    cudaGetSymbolAddress((void**)&k,    g_k);
    cudaGetSymbolAddress((void**)&v,    g_v);
    cudaGetSymbolAddress((void**)&attn, g_attn);
    cudaGetSymbolAddress((void**)&h1,   g_h1);
    cudaGetSymbolAddress((void**)&f1,   g_f1);

    cudaFuncSetAttribute(flash_kernel,
                         cudaFuncAttributeMaxDynamicSharedMemorySize, FLASH_SMEM);
    cudaFuncSetAttribute(gemm_tf32<0>,
                         cudaFuncAttributeMaxDynamicSharedMemorySize, GEMM_SMEM);
    cudaFuncSetAttribute(gemm_tf32<1>,
                         cudaFuncAttributeMaxDynamicSharedMemorySize, GEMM_SMEM);
    cudaFuncSetAttribute(gemm_tf32<2>,
                         cudaFuncAttributeMaxDynamicSharedMemorySize, GEMM_SMEM);

    // 1) LN1
    ln_kernel<<<NROWS, 256>>>(hidden, ln1_g, ln1_b, ln);

    // 2) Q, K, V projections
    dim3 gD(DD / 128, NROWS / 128);
    gemm_tf32<0><<<gD, 256, GEMM_SMEM>>>(ln, wq, bq, nullptr, q, NROWS, DD, DD);
    gemm_tf32<0><<<gD, 256, GEMM_SMEM>>>(ln, wk, bk, nullptr, k, NROWS, DD, DD);
    gemm_tf32<0><<<gD, 256, GEMM_SMEM>>>(ln, wv, bv, nullptr, v, NROWS, DD, DD);

    // 3) attention
    flash_kernel<<<dim3(SS / 64, HH, BB), 256, FLASH_SMEM>>>(q, k, v, mask, attn);

    // 4) output projection + residual
    gemm_tf32<2><<<gD, 256, GEMM_SMEM>>>(attn, wo, bo, hidden, h1, NROWS, DD, DD);

    // 5) LN2
    ln_kernel<<<NROWS, 256>>>(h1, ln2_g, ln2_b, ln);

    // 6) FFN
    dim3 gF(DFF / 128, NROWS / 128);
    gemm_tf32<1><<<gF, 256, GEMM_SMEM>>>(ln, w1, b1, nullptr, f1, NROWS, DD, DFF);
    gemm_tf32<2><<<gD, 256, GEMM_SMEM>>>(f1, w2, b2, h1, out, NROWS, DFF, DD);
}

// round 4
// speedup vs baseline: 3.2099x; 1.5948x over previous
#include <cuda_runtime.h>
#include <math.h>
#include <stdint.h>

#define BB 2
#define SS 2048
#define DD 1024
#define HH 16
#define DHD 64
#define DFF 4096
#define NROWS (BB * SS)

// ---------------- scratch (device globals; no allocation) ----------------
__device__ float g_ln[NROWS * DD];
__device__ float g_q[NROWS * DD];
__device__ float g_k[NROWS * DD];
__device__ float g_v[NROWS * DD];
__device__ float g_attn[NROWS * DD];
__device__ float g_h1[NROWS * DD];
__device__ float g_f1[NROWS * DFF];
__device__ float g_wqr[DD * DD];
__device__ float g_wkr[DD * DD];
__device__ float g_wvr[DD * DD];
__device__ float g_wor[DD * DD];
__device__ float g_w1r[DD * DFF];
__device__ float g_w2r[DFF * DD];

// ---------------- helpers --------------------------------------------------
__device__ __forceinline__ uint32_t to_tf32(float f) {
    uint32_t u;
    asm("cvt.rna.tf32.f32 %0, %1;" : "=r"(u) : "f"(f));
    return u;
}
__device__ __forceinline__ float rnaf(float f) { return __uint_as_float(to_tf32(f)); }

__device__ __forceinline__ void cp16(void* dst_smem, const void* src) {
    uint32_t d;
    asm("{ .reg .u64 t; cvta.to.shared.u64 t, %1; cvt.u32.u64 %0, t; }"
        : "=r"(d) : "l"(dst_smem));
    asm volatile("cp.async.cg.shared.global [%0], [%1], 16;" :: "r"(d), "l"(src));
}
__device__ __forceinline__ void cp_commit() {
    asm volatile("cp.async.commit_group;");
}
template <int N>
__device__ __forceinline__ void cp_wait() {
    asm volatile("cp.async.wait_group %0;" :: "n"(N));
}

__device__ __forceinline__ void mma8(float c[4], const uint32_t a[4], const uint32_t b[2]) {
    asm volatile(
        "mma.sync.aligned.m16n8k8.row.col.f32.tf32.tf32.f32 "
        "{%0,%1,%2,%3}, {%4,%5,%6,%7}, {%8,%9}, {%0,%1,%2,%3};"
        : "+f"(c[0]), "+f"(c[1]), "+f"(c[2]), "+f"(c[3])
        : "r"(a[0]), "r"(a[1]), "r"(a[2]), "r"(a[3]), "r"(b[0]), "r"(b[1]));
}

__device__ __forceinline__ float gelu_tanh_f(float h) {
    const float c = 0.7978845608028654f;
    float u = c * (h + 0.044715f * h * h * h);
    return 0.5f * h * (1.0f + tanhf(u));
}

// ---------------- weight rounding pack (one elementwise pass) --------------
__global__ void __launch_bounds__(256) wround_kernel(
    const float* __restrict__ in, float* __restrict__ out, int n4)
{
    int i = blockIdx.x * 256 + threadIdx.x;
    if (i < n4) {
        float4 v = ((const float4*)in)[i];
        uint4 o;
        o.x = to_tf32(v.x); o.y = to_tf32(v.y);
        o.z = to_tf32(v.z); o.w = to_tf32(v.w);
        ((uint4*)out)[i] = o;
    }
}

// ---------------- LayerNorm (Bessel var, eps on std) -> tf32-rounded out ---
__global__ void __launch_bounds__(256) ln_kernel(
    const float* __restrict__ x, const float* __restrict__ gw,
    const float* __restrict__ bw, float* __restrict__ y)
{
    int row = blockIdx.x;
    int t = threadIdx.x;
    const float4* xr = (const float4*)(x + (size_t)row * DD);
    float4 v = xr[t];
    float s  = v.x + v.y + v.z + v.w;
    float ss = v.x * v.x + v.y * v.y + v.z * v.z + v.w * v.w;

    __shared__ float rs[8], rss[8];
    #pragma unroll
    for (int o = 16; o; o >>= 1) {
        s  += __shfl_xor_sync(0xffffffffu, s,  o);
        ss += __shfl_xor_sync(0xffffffffu, ss, o);
    }
    if ((t & 31) == 0) { rs[t >> 5] = s; rss[t >> 5] = ss; }
    __syncthreads();
    __shared__ float mean_s, rd_s;
    if (t == 0) {
        float S = 0.f, SQ = 0.f;
        #pragma unroll
        for (int i = 0; i < 8; i++) { S += rs[i]; SQ += rss[i]; }
        float mean = S * (1.0f / DD);
        float var  = (SQ - S * S * (1.0f / DD)) * (1.0f / (DD - 1));
        var = fmaxf(var, 0.f);
        mean_s = mean;
        rd_s = 1.0f / (sqrtf(var) + 1e-6f);
    }
    __syncthreads();
    float mean = mean_s, rd = rd_s;
    float4 g4 = ((const float4*)gw)[t];
    float4 b4 = ((const float4*)bw)[t];
    uint4 o;
    o.x = to_tf32(g4.x * (v.x - mean) * rd + b4.x);
    o.y = to_tf32(g4.y * (v.y - mean) * rd + b4.y);
    o.z = to_tf32(g4.z * (v.z - mean) * rd + b4.z);
    o.w = to_tf32(g4.w * (v.w - mean) * rd + b4.w);
    ((uint4*)(y + (size_t)row * DD))[t] = o;
}

// ---------------- tf32 mma.sync GEMM (128x128x32, 8 warps) -----------------
#define TK 32
#define ASTR 36
#define BSTR 136
#define A_TILE_F (128 * ASTR)
#define B_TILE_F (TK * BSTR)
#define STAGE_F (A_TILE_F + B_TILE_F)
#define NSTG 3
#define GEMM_SMEM (NSTG * STAGE_F * 4)

// EPI: 1 = bias+gelu (tf32-rounded out), 2 = bias+residual (full fp32),
//      3 = bias (tf32-rounded out)
template <int EPI>
__global__ void __launch_bounds__(256) gemm_tf32(
    const float* __restrict__ A, const float* __restrict__ W,
    const float* __restrict__ bias, const float* __restrict__ R,
    float* __restrict__ C, int M, int K, int N)
{
    extern __shared__ float sm[];
    int t = threadIdx.x;
    int m0 = blockIdx.y * 128, n0 = blockIdx.x * 128;
    int nkt = K >> 5;

    auto load_tile = [&](int stg, int kt) {
        float* As = sm + stg * STAGE_F;
        float* Bs = As + A_TILE_F;
        int k0 = kt * TK;
        #pragma unroll
        for (int i = 0; i < 4; i++) {
            int id = t + i * 256;
            int row = id >> 3, c4 = (id & 7) << 2;
            cp16(As + row * ASTR + c4, A + (size_t)(m0 + row) * K + k0 + c4);
        }
        #pragma unroll
        for (int i = 0; i < 4; i++) {
            int id = t + i * 256;
            int row = id >> 5, c4 = (id & 31) << 2;
            cp16(Bs + row * BSTR + c4, W + (size_t)(k0 + row) * N + n0 + c4);
        }
    };

    float acc[4][4][4];
    #pragma unroll
    for (int mt = 0; mt < 4; mt++)
        #pragma unroll
        for (int nt = 0; nt < 4; nt++)
            #pragma unroll
            for (int i = 0; i < 4; i++) acc[mt][nt][i] = 0.f;

    int lane = t & 31, wid = t >> 5;
    int warpM = wid >> 2, warpN = wid & 3;
    int g = lane >> 2, c = lane & 3;
    int arow = warpM * 64 + g;
    int bcol = warpN * 32 + g;

    #pragma unroll
    for (int s = 0; s < NSTG; s++) { load_tile(s, s); cp_commit(); }

    for (int kt = 0; kt < nkt; kt++) {
        cp_wait<NSTG - 1>();
        __syncthreads();

        const float* As = sm + (kt % NSTG) * STAGE_F;
        const float* Bs = As + A_TILE_F;

        #pragma unroll
        for (int ks = 0; ks < 4; ks++) {
            int k0 = ks * 8;
            uint32_t af[4][4], bf[4][2];
            #pragma unroll
            for (int mt = 0; mt < 4; mt++) {
                const float* ap = As + (size_t)(arow + mt * 16) * ASTR + k0 + c;
                af[mt][0] = __float_as_uint(ap[0]);
                af[mt][1] = __float_as_uint(ap[8 * ASTR]);
                af[mt][2] = __float_as_uint(ap[4]);
                af[mt][3] = __float_as_uint(ap[8 * ASTR + 4]);
            }
            #pragma unroll
            for (int nt = 0; nt < 4; nt++) {
                const float* bp = Bs + (size_t)(k0 + c) * BSTR + bcol + nt * 8;
                bf[nt][0] = __float_as_uint(bp[0]);
                bf[nt][1] = __float_as_uint(bp[4 * BSTR]);
            }
            #pragma unroll
            for (int mt = 0; mt < 4; mt++)
                #pragma unroll
                for (int nt = 0; nt < 4; nt++)
                    mma8(acc[mt][nt], af[mt], bf[nt]);
        }

        __syncthreads();
        int nx = kt + NSTG;
        if (nx < nkt) load_tile(kt % NSTG, nx);
        cp_commit();
    }

    int rbase = m0 + warpM * 64 + g;
    int cbase = n0 + warpN * 32 + 2 * c;

    #pragma unroll
    for (int nt = 0; nt < 4; nt++) {
        int col = cbase + nt * 8;
        float2 b2 = *(const float2*)(bias + col);
        #pragma unroll
        for (int mt = 0; mt < 4; mt++) {
            int r0 = rbase + mt * 16;
            float v0x = acc[mt][nt][0] + b2.x;
            float v0y = acc[mt][nt][1] + b2.y;
            float v1x = acc[mt][nt][2] + b2.x;
            float v1y = acc[mt][nt][3] + b2.y;
            if (EPI == 1) {
                v0x = rnaf(gelu_tanh_f(v0x)); v0y = rnaf(gelu_tanh_f(v0y));
                v1x = rnaf(gelu_tanh_f(v1x)); v1y = rnaf(gelu_tanh_f(v1y));
            }
            if (EPI == 3) {
                v0x = rnaf(v0x); v0y = rnaf(v0y);
                v1x = rnaf(v1x); v1y = rnaf(v1y);
            }
            if (EPI == 2) {
                float2 r0v = *(const float2*)(R + (size_t)r0 * N + col);
                float2 r1v = *(const float2*)(R + (size_t)(r0 + 8) * N + col);
                v0x += r0v.x; v0y += r0v.y; v1x += r1v.x; v1y += r1v.y;
            }
            *(float2*)(C + (size_t)r0 * N + col)       = make_float2(v0x, v0y);
            *(float2*)(C + (size_t)(r0 + 8) * N + col) = make_float2(v1x, v1y);
        }
    }
}

// ---------------- tensor-core flash attention ------------------------------
// CTA: 128 q-rows x full head (d=64); 8 warps, each 16 q-rows (warp-local
// softmax). K/V 64-row tiles, double-buffered cp.async. P via per-warp smem.
#define FSTR 72
#define KV_TILE_F (64 * FSTR)
#define QP_OFF 0
#define K_OFF (128 * FSTR)
#define V_OFF (K_OFF + 2 * KV_TILE_F)
#define M_OFF (V_OFF + 2 * KV_TILE_F)
#define FLASH_SMEM ((M_OFF + 2 * 64) * 4)

__global__ void __launch_bounds__(256) flash_tc(
    const float* __restrict__ Q, const float* __restrict__ Kg,
    const float* __restrict__ Vg, const int* __restrict__ mask,
    float* __restrict__ O)
{
    extern __shared__ float sm[];
    int t = threadIdx.x;
    int lane = t & 31, wid = t >> 5;
    int g = lane >> 2, c = lane & 3;
    int q0 = blockIdx.x * 128;
    int h = blockIdx.y, b = blockIdx.z;
    size_t baseQ = ((size_t)(b * SS + q0)) * DD + h * DHD;

    auto load_kv = [&](int kt, int s) {
        size_t baseK = ((size_t)(b * SS + kt * 64)) * DD + h * DHD;
        float* Kb = sm + K_OFF + s * KV_TILE_F;
        float* Vb = sm + V_OFF + s * KV_TILE_F;
        #pragma unroll
        for (int i = 0; i < 4; i++) {
            int id = t + i * 256;
            int row = id >> 4, c4 = (id & 15) << 2;
            cp16(Kb + row * FSTR + c4, Kg + baseK + (size_t)row * DD + c4);
            cp16(Vb + row * FSTR + c4, Vg + baseK + (size_t)row * DD + c4);
        }
        if (t < 16) {
            int* mb = (int*)(sm + M_OFF) + s * 64;
            cp16(mb + t * 4, mask + b * SS + kt * 64 + t * 4);
        }
    };

    load_kv(0, 0);
    cp_commit();
    #pragma unroll
    for (int i = 0; i < 8; i++) {
        int id = t + i * 256;
        int row = id >> 4, c4 = (id & 15) << 2;
        cp16(sm + QP_OFF + row * FSTR + c4, Q + baseQ + (size_t)row * DD + c4);
    }
    cp_commit();
    load_kv(1, 1);
    cp_commit();

    cp_wait<1>();
    __syncthreads();

    // Q fragments with folded 1/sqrt(64) scale (exact power-of-2 scaling)
    uint32_t qf[8][4];
    int qbase = wid * 16;
    #pragma unroll
    for (int ks = 0; ks < 8; ks++) {
        const float* qp = sm + QP_OFF + (size_t)(qbase + g) * FSTR + ks * 8 + c;
        qf[ks][0] = __float_as_uint(qp[0] * 0.125f);
        qf[ks][1] = __float_as_uint(qp[8 * FSTR] * 0.125f);
        qf[ks][2] = __float_as_uint(qp[4] * 0.125f);
        qf[ks][3] = __float_as_uint(qp[8 * FSTR + 4] * 0.125f);
    }
    __syncthreads();   // Qs region becomes P region

    float m0 = -1e30f, m1 = -1e30f, l0 = 0.f, l1 = 0.f;
    float acc[8][4];
    #pragma unroll
    for (int nt = 0; nt < 8; nt++)
        #pragma unroll
        for (int i = 0; i < 4; i++) acc[nt][i] = 0.f;

    float* Pw = sm + QP_OFF + (size_t)wid * 16 * FSTR;

    for (int kt = 0; kt < SS / 64; kt++) {
        cp_wait<1>();
        __syncthreads();
        const float* Ks = sm + K_OFF + (kt & 1) * KV_TILE_F;
        const float* Vs = sm + V_OFF + (kt & 1) * KV_TILE_F;
        const int* mk = (const int*)(sm + M_OFF) + (kt & 1) * 64;

        // S = Q K^T (scaled)
        float sf[8][4];
        #pragma unroll
        for (int nt = 0; nt < 8; nt++)
            #pragma unroll
            for (int i = 0; i < 4; i++) sf[nt][i] = 0.f;

        #pragma unroll
        for (int nt = 0; nt < 8; nt++) {
            #pragma unroll
            for (int ks = 0; ks < 8; ks++) {
                const float* kp = Ks + (size_t)(nt * 8 + g) * FSTR + ks * 8 + c;
                uint32_t bb[2];
                bb[0] = __float_as_uint(kp[0]);
                bb[1] = __float_as_uint(kp[4]);
                mma8(sf[nt], qf[ks], bb);
            }
        }

        // mask bias + online softmax (rows g and g+8, warp-local)
        float mx0 = -1e30f, mx1 = -1e30f;
        #pragma unroll
        for (int nt = 0; nt < 8; nt++) {
            float bia0 = mk[nt * 8 + 2 * c]     ? 0.f : -1e9f;
            float bia1 = mk[nt * 8 + 2 * c + 1] ? 0.f : -1e9f;
            sf[nt][0] += bia0; sf[nt][1] += bia1;
            sf[nt][2] += bia0; sf[nt][3] += bia1;
            mx0 = fmaxf(mx0, fmaxf(sf[nt][0], sf[nt][1]));
            mx1 = fmaxf(mx1, fmaxf(sf[nt][2], sf[nt][3]));
        }
        mx0 = fmaxf(mx0, __shfl_xor_sync(0xffffffffu, mx0, 1));
        mx0 = fmaxf(mx0, __shfl_xor_sync(0xffffffffu, mx0, 2));
        mx1 = fmaxf(mx1, __shfl_xor_sync(0xffffffffu, mx1, 1));
        mx1 = fmaxf(mx1, __shfl_xor_sync(0xffffffffu, mx1, 2));

        float mn0 = fmaxf(m0, mx0), mn1 = fmaxf(m1, mx1);
        float al0 = __expf(m0 - mn0), al1 = __expf(m1 - mn1);
        m0 = mn0; m1 = mn1;

        float ps0 = 0.f, ps1 = 0.f;
        #pragma unroll
        for (int nt = 0; nt < 8; nt++) {
            sf[nt][0] = __expf(sf[nt][0] - mn0);
            sf[nt][1] = __expf(sf[nt][1] - mn0);
            sf[nt][2] = __expf(sf[nt][2] - mn1);
            sf[nt][3] = __expf(sf[nt][3] - mn1);
            ps0 += sf[nt][0] + sf[nt][1];
            ps1 += sf[nt][2] + sf[nt][3];
        }
        ps0 += __shfl_xor_sync(0xffffffffu, ps0, 1);
        ps0 += __shfl_xor_sync(0xffffffffu, ps0, 2);
        ps1 += __shfl_xor_sync(0xffffffffu, ps1, 1);
        ps1 += __shfl_xor_sync(0xffffffffu, ps1, 2);
        l0 = l0 * al0 + ps0;
        l1 = l1 * al1 + ps1;

        #pragma unroll
        for (int nt = 0; nt < 8; nt++) {
            acc[nt][0] *= al0; acc[nt][1] *= al0;
            acc[nt][2] *= al1; acc[nt][3] *= al1;
        }

        // store P (tf32-rounded) into per-warp smem
        #pragma unroll
        for (int nt = 0; nt < 8; nt++) {
            uint2 p0 = make_uint2(to_tf32(sf[nt][0]), to_tf32(sf[nt][1]));
            uint2 p1 = make_uint2(to_tf32(sf[nt][2]), to_tf32(sf[nt][3]));
            *(uint2*)&Pw[(size_t)g * FSTR + nt * 8 + 2 * c]        = p0;
            *(uint2*)&Pw[(size_t)(g + 8) * FSTR + nt * 8 + 2 * c]  = p1;
        }
        __syncwarp();

        // acc += P V
        #pragma unroll
        for (int ks = 0; ks < 8; ks++) {
            uint32_t pa[4];
            pa[0] = __float_as_uint(Pw[(size_t)g * FSTR + ks * 8 + c]);
            pa[1] = __float_as_uint(Pw[(size_t)(g + 8) * FSTR + ks * 8 + c]);
            pa[2] = __float_as_uint(Pw[(size_t)g * FSTR + ks * 8 + c + 4]);
            pa[3] = __float_as_uint(Pw[(size_t)(g + 8) * FSTR + ks * 8 + c + 4]);
            #pragma unroll
            for (int nt = 0; nt < 8; nt++) {
                const float* vp = Vs + (size_t)(ks * 8 + c) * FSTR + nt * 8 + g;
                uint32_t bb[2];
                bb[0] = __float_as_uint(vp[0]);
                bb[1] = __float_as_uint(vp[4 * FSTR]);
                mma8(acc[nt], pa, bb);
            }
        }

        __syncthreads();
        if (kt + 2 < SS / 64) load_kv(kt + 2, kt & 1);
        cp_commit();
    }

    // epilogue: normalize, tf32-round (feeds wo GEMM), store
    float inv0 = 1.f / l0, inv1 = 1.f / l1;
    size_t r0 = ((size_t)(b * SS + q0 + qbase + g)) * DD + h * DHD;
    size_t r1 = r0 + 8 * DD;
    #pragma unroll
    for (int nt = 0; nt < 8; nt++) {
        int col = nt * 8 + 2 * c;
        *(float2*)(O + r0 + col) =
            make_float2(rnaf(acc[nt][0] * inv0), rnaf(acc[nt][1] * inv0));
        *(float2*)(O + r1 + col) =
            make_float2(rnaf(acc[nt][2] * inv1), rnaf(acc[nt][3] * inv1));
    }
}

// ---------------- launch ---------------------------------------------------
extern "C" void kernel_launch(void* const* d_in, const int* in_sizes, int n_in,
                              void* d_out, int out_size)
{
    const float* hidden = (const float*)d_in[0];
    const int*   mask   = (const int*)d_in[1];
    const float* wq = (const float*)d_in[2];
    const float* bq = (const float*)d_in[3];
    const float* wk = (const float*)d_in[4];
    const float* bk = (const float*)d_in[5];
    const float* wv = (const float*)d_in[6];
    const float* bv = (const float*)d_in[7];
    const float* wo = (const float*)d_in[8];
    const float* bo = (const float*)d_in[9];
    const float* w1 = (const float*)d_in[10];
    const float* b1 = (const float*)d_in[11];
    const float* w2 = (const float*)d_in[12];
    const float* b2 = (const float*)d_in[13];
    const float* ln1_g = (const float*)d_in[14];
    const float* ln1_b = (const float*)d_in[15];
    const float* ln2_g = (const float*)d_in[16];
    const float* ln2_b = (const float*)d_in[17];
    float* out = (float*)d_out;

    float *ln, *q, *k, *v, *attn, *h1, *f1;
    float *wqr, *wkr, *wvr, *wor, *w1r, *w2r;
    cudaGetSymbolAddress((void**)&ln,   g_ln);
    cudaGetSymbolAddress((void**)&q,    g_q);
    cudaGetSymbolAddress((void**)&k,    g_k);
    cudaGetSymbolAddress((void**)&v,    g_v);
    cudaGetSymbolAddress((void**)&attn, g_attn);
    cudaGetSymbolAddress((void**)&h1,   g_h1);
    cudaGetSymbolAddress((void**)&f1,   g_f1);
    cudaGetSymbolAddress((void**)&wqr,  g_wqr);
    cudaGetSymbolAddress((void**)&wkr,  g_wkr);
    cudaGetSymbolAddress((void**)&wvr,  g_wvr);
    cudaGetSymbolAddress((void**)&wor,  g_wor);
    cudaGetSymbolAddress((void**)&w1r,  g_w1r);
    cudaGetSymbolAddress((void**)&w2r,  g_w2r);

    cudaFuncSetAttribute(flash_tc,
                         cudaFuncAttributeMaxDynamicSharedMemorySize, FLASH_SMEM);
    cudaFuncSetAttribute(gemm_tf32<1>,
                         cudaFuncAttributeMaxDynamicSharedMemorySize, GEMM_SMEM);
    cudaFuncSetAttribute(gemm_tf32<2>,
                         cudaFuncAttributeMaxDynamicSharedMemorySize, GEMM_SMEM);
    cudaFuncSetAttribute(gemm_tf32<3>,
                         cudaFuncAttributeMaxDynamicSharedMemorySize, GEMM_SMEM);

    // one-time-per-call rna rounding of weights (removes truncation bias)
    wround_kernel<<<(DD * DD / 4 + 255) / 256, 256>>>(wq, wqr, DD * DD / 4);
    wround_kernel<<<(DD * DD / 4 + 255) / 256, 256>>>(wk, wkr, DD * DD / 4);
    wround_kernel<<<(DD * DD / 4 + 255) / 256, 256>>>(wv, wvr, DD * DD / 4);
    wround_kernel<<<(DD * DD / 4 + 255) / 256, 256>>>(wo, wor, DD * DD / 4);
    wround_kernel<<<(DD * DFF / 4 + 255) / 256, 256>>>(w1, w1r, DD * DFF / 4);
    wround_kernel<<<(DFF * DD / 4 + 255) / 256, 256>>>(w2, w2r, DFF * DD / 4);

    // 1) LN1 (tf32-rounded out)
    ln_kernel<<<NROWS, 256>>>(hidden, ln1_g, ln1_b, ln);

    // 2) Q, K, V projections (tf32-rounded out)
    dim3 gD(DD / 128, NROWS / 128);
    gemm_tf32<3><<<gD, 256, GEMM_SMEM>>>(ln, wqr, bq, nullptr, q, NROWS, DD, DD);
    gemm_tf32<3><<<gD, 256, GEMM_SMEM>>>(ln, wkr, bk, nullptr, k, NROWS, DD, DD);
    gemm_tf32<3><<<gD, 256, GEMM_SMEM>>>(ln, wvr, bv, nullptr, v, NROWS, DD, DD);

    // 3) attention (tensor-core flash)
    flash_tc<<<dim3(SS / 128, HH, BB), 256, FLASH_SMEM>>>(q, k, v, mask, attn);

    // 4) output projection + residual (full fp32 out)
    gemm_tf32<2><<<gD, 256, GEMM_SMEM>>>(attn, wor, bo, hidden, h1, NROWS, DD, DD);

    // 5) LN2 (tf32-rounded out)
    ln_kernel<<<NROWS, 256>>>(h1, ln2_g, ln2_b, ln);

    // 6) FFN
    dim3 gF(DFF / 128, NROWS / 128);
    gemm_tf32<1><<<gF, 256, GEMM_SMEM>>>(ln, w1r, b1, nullptr, f1, NROWS, DD, DFF);
    gemm_tf32<2><<<gD, 256, GEMM_SMEM>>>(f1, w2r, b2, h1, out, NROWS, DFF, DD);
}

// round 5
// speedup vs baseline: 3.3636x; 1.0479x over previous
#include <cuda_runtime.h>
#include <math.h>
#include <stdint.h>

#define BB 2
#define SS 2048
#define DD 1024
#define HH 16
#define DHD 64
#define DFF 4096
#define NROWS (BB * SS)
#define NQKV 3072

// ---------------- scratch (device globals; no allocation) ----------------
__device__ float g_ln[NROWS * DD];
__device__ float g_qkv[NROWS * NQKV];
__device__ float g_attn[NROWS * DD];
__device__ float g_h1[NROWS * DD];
__device__ float g_f1[NROWS * DFF];
__device__ float g_wqkv[DD * NQKV];
__device__ float g_bqkv[NQKV];
__device__ float g_wor[DD * DD];
__device__ float g_w1r[DD * DFF];
__device__ float g_w2r[DFF * DD];

// ---------------- helpers --------------------------------------------------
__device__ __forceinline__ uint32_t to_tf32(float f) {
    uint32_t u;
    asm("cvt.rna.tf32.f32 %0, %1;" : "=r"(u) : "f"(f));
    return u;
}
__device__ __forceinline__ float rnaf(float f) { return __uint_as_float(to_tf32(f)); }

__device__ __forceinline__ void cp16(void* dst_smem, const void* src) {
    uint32_t d;
    asm("{ .reg .u64 t; cvta.to.shared.u64 t, %1; cvt.u32.u64 %0, t; }"
        : "=r"(d) : "l"(dst_smem));
    asm volatile("cp.async.cg.shared.global [%0], [%1], 16;" :: "r"(d), "l"(src));
}
__device__ __forceinline__ void cp_commit() {
    asm volatile("cp.async.commit_group;");
}
template <int N>
__device__ __forceinline__ void cp_wait() {
    asm volatile("cp.async.wait_group %0;" :: "n"(N));
}

__device__ __forceinline__ void mma8(float c[4], const uint32_t a[4], const uint32_t b[2]) {
    asm volatile(
        "mma.sync.aligned.m16n8k8.row.col.f32.tf32.tf32.f32 "
        "{%0,%1,%2,%3}, {%4,%5,%6,%7}, {%8,%9}, {%0,%1,%2,%3};"
        : "+f"(c[0]), "+f"(c[1]), "+f"(c[2]), "+f"(c[3])
        : "r"(a[0]), "r"(a[1]), "r"(a[2]), "r"(a[3]), "r"(b[0]), "r"(b[1]));
}

__device__ __forceinline__ float gelu_tanh_f(float h) {
    const float c = 0.7978845608028654f;
    float u = c * (h + 0.044715f * h * h * h);
    return 0.5f * h * (1.0f + tanhf(u));
}

// ---------------- weight rounding packs ------------------------------------
__global__ void __launch_bounds__(256) wround_kernel(
    const float* __restrict__ in, float* __restrict__ out, int n4)
{
    int i = blockIdx.x * 256 + threadIdx.x;
    if (i < n4) {
        float4 v = ((const float4*)in)[i];
        uint4 o;
        o.x = to_tf32(v.x); o.y = to_tf32(v.y);
        o.z = to_tf32(v.z); o.w = to_tf32(v.w);
        ((uint4*)out)[i] = o;
    }
}

// strided pack: in [K x 1024] -> out rows of 3072, at column offset
__global__ void __launch_bounds__(256) wround_qkv_kernel(
    const float* __restrict__ in, float* __restrict__ out, int coff)
{
    int i = blockIdx.x * 256 + threadIdx.x;  // over DD*DD/4
    int row = i >> 8, c4 = (i & 255) << 2;
    float4 v = ((const float4*)in)[i];
    uint4 o;
    o.x = to_tf32(v.x); o.y = to_tf32(v.y);
    o.z = to_tf32(v.z); o.w = to_tf32(v.w);
    *(uint4*)(out + (size_t)row * NQKV + coff + c4) = o;
}

__global__ void __launch_bounds__(256) bpack_kernel(
    const float* __restrict__ bq, const float* __restrict__ bk,
    const float* __restrict__ bv, float* __restrict__ out)
{
    int i = blockIdx.x * 256 + threadIdx.x;
    if (i < DD) {
        out[i] = bq[i];
        out[DD + i] = bk[i];
        out[2 * DD + i] = bv[i];
    }
}

// ---------------- LayerNorm (Bessel var, eps on std) -> tf32-rounded out ---
__global__ void __launch_bounds__(256) ln_kernel(
    const float* __restrict__ x, const float* __restrict__ gw,
    const float* __restrict__ bw, float* __restrict__ y)
{
    int row = blockIdx.x;
    int t = threadIdx.x;
    const float4* xr = (const float4*)(x + (size_t)row * DD);
    float4 v = xr[t];
    float s  = v.x + v.y + v.z + v.w;
    float ss = v.x * v.x + v.y * v.y + v.z * v.z + v.w * v.w;

    __shared__ float rs[8], rss[8];
    #pragma unroll
    for (int o = 16; o; o >>= 1) {
        s  += __shfl_xor_sync(0xffffffffu, s,  o);
        ss += __shfl_xor_sync(0xffffffffu, ss, o);
    }
    if ((t & 31) == 0) { rs[t >> 5] = s; rss[t >> 5] = ss; }
    __syncthreads();
    __shared__ float mean_s, rd_s;
    if (t == 0) {
        float S = 0.f, SQ = 0.f;
        #pragma unroll
        for (int i = 0; i < 8; i++) { S += rs[i]; SQ += rss[i]; }
        float mean = S * (1.0f / DD);
        float var  = (SQ - S * S * (1.0f / DD)) * (1.0f / (DD - 1));
        var = fmaxf(var, 0.f);
        mean_s = mean;
        rd_s = 1.0f / (sqrtf(var) + 1e-6f);
    }
    __syncthreads();
    float mean = mean_s, rd = rd_s;
    float4 g4 = ((const float4*)gw)[t];
    float4 b4 = ((const float4*)bw)[t];
    uint4 o;
    o.x = to_tf32(g4.x * (v.x - mean) * rd + b4.x);
    o.y = to_tf32(g4.y * (v.y - mean) * rd + b4.y);
    o.z = to_tf32(g4.z * (v.z - mean) * rd + b4.z);
    o.w = to_tf32(g4.w * (v.w - mean) * rd + b4.w);
    ((uint4*)(y + (size_t)row * DD))[t] = o;
}

// ---------------- tf32 mma.sync GEMM (128x128x32, 8 warps, 2 CTA/SM) -------
#define TK 32
#define ASTR 36
#define BSTR 136
#define A_TILE_F (128 * ASTR)
#define B_TILE_F (TK * BSTR)
#define STAGE_F (A_TILE_F + B_TILE_F)
#define NSTG 2
#define GEMM_SMEM (NSTG * STAGE_F * 4)

// EPI: 1 = bias+gelu (tf32-rounded out), 2 = bias+residual (full fp32),
//      3 = bias (tf32-rounded out)
template <int EPI>
__global__ void __launch_bounds__(256, 2) gemm_tf32(
    const float* __restrict__ A, const float* __restrict__ W,
    const float* __restrict__ bias, const float* __restrict__ R,
    float* __restrict__ C, int M, int K, int N)
{
    extern __shared__ float sm[];
    int t = threadIdx.x;
    int m0 = blockIdx.y * 128, n0 = blockIdx.x * 128;
    int nkt = K >> 5;

    auto load_tile = [&](int stg, int kt) {
        float* As = sm + stg * STAGE_F;
        float* Bs = As + A_TILE_F;
        int k0 = kt * TK;
        #pragma unroll
        for (int i = 0; i < 4; i++) {
            int id = t + i * 256;
            int row = id >> 3, c4 = (id & 7) << 2;
            cp16(As + row * ASTR + c4, A + (size_t)(m0 + row) * K + k0 + c4);
        }
        #pragma unroll
        for (int i = 0; i < 4; i++) {
            int id = t + i * 256;
            int row = id >> 5, c4 = (id & 31) << 2;
            cp16(Bs + row * BSTR + c4, W + (size_t)(k0 + row) * N + n0 + c4);
        }
    };

    float acc[4][4][4];
    #pragma unroll
    for (int mt = 0; mt < 4; mt++)
        #pragma unroll
        for (int nt = 0; nt < 4; nt++)
            #pragma unroll
            for (int i = 0; i < 4; i++) acc[mt][nt][i] = 0.f;

    int lane = t & 31, wid = t >> 5;
    int warpM = wid >> 2, warpN = wid & 3;
    int g = lane >> 2, c = lane & 3;
    int arow = warpM * 64 + g;
    int bcol = warpN * 32 + g;

    #pragma unroll
    for (int s = 0; s < NSTG; s++) { load_tile(s, s); cp_commit(); }

    for (int kt = 0; kt < nkt; kt++) {
        cp_wait<NSTG - 1>();
        __syncthreads();

        const float* As = sm + (kt % NSTG) * STAGE_F;
        const float* Bs = As + A_TILE_F;

        #pragma unroll
        for (int ks = 0; ks < 4; ks++) {
            int k0 = ks * 8;
            uint32_t af[4][4], bf[4][2];
            #pragma unroll
            for (int mt = 0; mt < 4; mt++) {
                const float* ap = As + (size_t)(arow + mt * 16) * ASTR + k0 + c;
                af[mt][0] = __float_as_uint(ap[0]);
                af[mt][1] = __float_as_uint(ap[8 * ASTR]);
                af[mt][2] = __float_as_uint(ap[4]);
                af[mt][3] = __float_as_uint(ap[8 * ASTR + 4]);
            }
            #pragma unroll
            for (int nt = 0; nt < 4; nt++) {
                const float* bp = Bs + (size_t)(k0 + c) * BSTR + bcol + nt * 8;
                bf[nt][0] = __float_as_uint(bp[0]);
                bf[nt][1] = __float_as_uint(bp[4 * BSTR]);
            }
            #pragma unroll
            for (int mt = 0; mt < 4; mt++)
                #pragma unroll
                for (int nt = 0; nt < 4; nt++)
                    mma8(acc[mt][nt], af[mt], bf[nt]);
        }

        __syncthreads();
        int nx = kt + NSTG;
        if (nx < nkt) load_tile(kt % NSTG, nx);
        cp_commit();
    }

    int rbase = m0 + warpM * 64 + g;
    int cbase = n0 + warpN * 32 + 2 * c;

    #pragma unroll
    for (int nt = 0; nt < 4; nt++) {
        int col = cbase + nt * 8;
        float2 b2 = *(const float2*)(bias + col);
        #pragma unroll
        for (int mt = 0; mt < 4; mt++) {
            int r0 = rbase + mt * 16;
            float v0x = acc[mt][nt][0] + b2.x;
            float v0y = acc[mt][nt][1] + b2.y;
            float v1x = acc[mt][nt][2] + b2.x;
            float v1y = acc[mt][nt][3] + b2.y;
            if (EPI == 1) {
                v0x = rnaf(gelu_tanh_f(v0x)); v0y = rnaf(gelu_tanh_f(v0y));
                v1x = rnaf(gelu_tanh_f(v1x)); v1y = rnaf(gelu_tanh_f(v1y));
            }
            if (EPI == 3) {
                v0x = rnaf(v0x); v0y = rnaf(v0y);
                v1x = rnaf(v1x); v1y = rnaf(v1y);
            }
            if (EPI == 2) {
                float2 r0v = *(const float2*)(R + (size_t)r0 * N + col);
                float2 r1v = *(const float2*)(R + (size_t)(r0 + 8) * N + col);
                v0x += r0v.x; v0y += r0v.y; v1x += r1v.x; v1y += r1v.y;
            }
            *(float2*)(C + (size_t)r0 * N + col)       = make_float2(v0x, v0y);
            *(float2*)(C + (size_t)(r0 + 8) * N + col) = make_float2(v1x, v1y);
        }
    }
}

// ---------------- tensor-core flash attention ------------------------------
#define FSTR 72
#define KV_TILE_F (64 * FSTR)
#define QP_OFF 0
#define K_OFF (128 * FSTR)
#define V_OFF (K_OFF + 2 * KV_TILE_F)
#define M_OFF (V_OFF + 2 * KV_TILE_F)
#define FLASH_SMEM ((M_OFF + 2 * 64) * 4)

__global__ void __launch_bounds__(256, 2) flash_tc(
    const float* __restrict__ Q, const float* __restrict__ Kg,
    const float* __restrict__ Vg, int ldq, const int* __restrict__ mask,
    float* __restrict__ O)
{
    extern __shared__ float sm[];
    int t = threadIdx.x;
    int lane = t & 31, wid = t >> 5;
    int g = lane >> 2, c = lane & 3;
    int q0 = blockIdx.x * 128;
    int h = blockIdx.y, b = blockIdx.z;
    size_t baseQ = ((size_t)(b * SS + q0)) * ldq + h * DHD;

    auto load_kv = [&](int kt, int s) {
        size_t baseK = ((size_t)(b * SS + kt * 64)) * ldq + h * DHD;
        float* Kb = sm + K_OFF + s * KV_TILE_F;
        float* Vb = sm + V_OFF + s * KV_TILE_F;
        #pragma unroll
        for (int i = 0; i < 4; i++) {
            int id = t + i * 256;
            int row = id >> 4, c4 = (id & 15) << 2;
            cp16(Kb + row * FSTR + c4, Kg + baseK + (size_t)row * ldq + c4);
            cp16(Vb + row * FSTR + c4, Vg + baseK + (size_t)row * ldq + c4);
        }
        if (t < 16) {
            int* mb = (int*)(sm + M_OFF) + s * 64;
            cp16(mb + t * 4, mask + b * SS + kt * 64 + t * 4);
        }
    };

    load_kv(0, 0);
    cp_commit();
    #pragma unroll
    for (int i = 0; i < 8; i++) {
        int id = t + i * 256;
        int row = id >> 4, c4 = (id & 15) << 2;
        cp16(sm + QP_OFF + row * FSTR + c4, Q + baseQ + (size_t)row * ldq + c4);
    }
    cp_commit();
    load_kv(1, 1);
    cp_commit();

    cp_wait<1>();
    __syncthreads();

    uint32_t qf[8][4];
    int qbase = wid * 16;
    #pragma unroll
    for (int ks = 0; ks < 8; ks++) {
        const float* qp = sm + QP_OFF + (size_t)(qbase + g) * FSTR + ks * 8 + c;
        qf[ks][0] = __float_as_uint(qp[0] * 0.125f);
        qf[ks][1] = __float_as_uint(qp[8 * FSTR] * 0.125f);
        qf[ks][2] = __float_as_uint(qp[4] * 0.125f);
        qf[ks][3] = __float_as_uint(qp[8 * FSTR + 4] * 0.125f);
    }
    __syncthreads();

    float m0 = -1e30f, m1 = -1e30f, l0 = 0.f, l1 = 0.f;
    float acc[8][4];
    #pragma unroll
    for (int nt = 0; nt < 8; nt++)
        #pragma unroll
        for (int i = 0; i < 4; i++) acc[nt][i] = 0.f;

    float* Pw = sm + QP_OFF + (size_t)wid * 16 * FSTR;

    for (int kt = 0; kt < SS / 64; kt++) {
        cp_wait<1>();
        __syncthreads();
        const float* Ks = sm + K_OFF + (kt & 1) * KV_TILE_F;
        const float* Vs = sm + V_OFF + (kt & 1) * KV_TILE_F;
        const int* mk = (const int*)(sm + M_OFF) + (kt & 1) * 64;

        float sf[8][4];
        #pragma unroll
        for (int nt = 0; nt < 8; nt++)
            #pragma unroll
            for (int i = 0; i < 4; i++) sf[nt][i] = 0.f;

        #pragma unroll
        for (int nt = 0; nt < 8; nt++) {
            #pragma unroll
            for (int ks = 0; ks < 8; ks++) {
                const float* kp = Ks + (size_t)(nt * 8 + g) * FSTR + ks * 8 + c;
                uint32_t bb[2];
                bb[0] = __float_as_uint(kp[0]);
                bb[1] = __float_as_uint(kp[4]);
                mma8(sf[nt], qf[ks], bb);
            }
        }

        float mx0 = -1e30f, mx1 = -1e30f;
        #pragma unroll
        for (int nt = 0; nt < 8; nt++) {
            float bia0 = mk[nt * 8 + 2 * c]     ? 0.f : -1e9f;
            float bia1 = mk[nt * 8 + 2 * c + 1] ? 0.f : -1e9f;
            sf[nt][0] += bia0; sf[nt][1] += bia1;
            sf[nt][2] += bia0; sf[nt][3] += bia1;
            mx0 = fmaxf(mx0, fmaxf(sf[nt][0], sf[nt][1]));
            mx1 = fmaxf(mx1, fmaxf(sf[nt][2], sf[nt][3]));
        }
        mx0 = fmaxf(mx0, __shfl_xor_sync(0xffffffffu, mx0, 1));
        mx0 = fmaxf(mx0, __shfl_xor_sync(0xffffffffu, mx0, 2));
        mx1 = fmaxf(mx1, __shfl_xor_sync(0xffffffffu, mx1, 1));
        mx1 = fmaxf(mx1, __shfl_xor_sync(0xffffffffu, mx1, 2));

        float mn0 = fmaxf(m0, mx0), mn1 = fmaxf(m1, mx1);
        float al0 = __expf(m0 - mn0), al1 = __expf(m1 - mn1);
        m0 = mn0; m1 = mn1;

        float ps0 = 0.f, ps1 = 0.f;
        #pragma unroll
        for (int nt = 0; nt < 8; nt++) {
            sf[nt][0] = __expf(sf[nt][0] - mn0);
            sf[nt][1] = __expf(sf[nt][1] - mn0);
            sf[nt][2] = __expf(sf[nt][2] - mn1);
            sf[nt][3] = __expf(sf[nt][3] - mn1);
            ps0 += sf[nt][0] + sf[nt][1];
            ps1 += sf[nt][2] + sf[nt][3];
        }
        ps0 += __shfl_xor_sync(0xffffffffu, ps0, 1);
        ps0 += __shfl_xor_sync(0xffffffffu, ps0, 2);
        ps1 += __shfl_xor_sync(0xffffffffu, ps1, 1);
        ps1 += __shfl_xor_sync(0xffffffffu, ps1, 2);
        l0 = l0 * al0 + ps0;
        l1 = l1 * al1 + ps1;

        #pragma unroll
        for (int nt = 0; nt < 8; nt++) {
            acc[nt][0] *= al0; acc[nt][1] *= al0;
            acc[nt][2] *= al1; acc[nt][3] *= al1;
        }

        #pragma unroll
        for (int nt = 0; nt < 8; nt++) {
            uint2 p0 = make_uint2(to_tf32(sf[nt][0]), to_tf32(sf[nt][1]));
            uint2 p1 = make_uint2(to_tf32(sf[nt][2]), to_tf32(sf[nt][3]));
            *(uint2*)&Pw[(size_t)g * FSTR + nt * 8 + 2 * c]        = p0;
            *(uint2*)&Pw[(size_t)(g + 8) * FSTR + nt * 8 + 2 * c]  = p1;
        }
        __syncwarp();

        #pragma unroll
        for (int ks = 0; ks < 8; ks++) {
            uint32_t pa[4];
            pa[0] = __float_as_uint(Pw[(size_t)g * FSTR + ks * 8 + c]);
            pa[1] = __float_as_uint(Pw[(size_t)(g + 8) * FSTR + ks * 8 + c]);
            pa[2] = __float_as_uint(Pw[(size_t)g * FSTR + ks * 8 + c + 4]);
            pa[3] = __float_as_uint(Pw[(size_t)(g + 8) * FSTR + ks * 8 + c + 4]);
            #pragma unroll
            for (int nt = 0; nt < 8; nt++) {
                const float* vp = Vs + (size_t)(ks * 8 + c) * FSTR + nt * 8 + g;
                uint32_t bb[2];
                bb[0] = __float_as_uint(vp[0]);
                bb[1] = __float_as_uint(vp[4 * FSTR]);
                mma8(acc[nt], pa, bb);
            }
        }

        __syncthreads();
        if (kt + 2 < SS / 64) load_kv(kt + 2, kt & 1);
        cp_commit();
    }

    float inv0 = 1.f / l0, inv1 = 1.f / l1;
    size_t r0 = ((size_t)(b * SS + q0 + qbase + g)) * DD + h * DHD;
    size_t r1 = r0 + 8 * DD;
    #pragma unroll
    for (int nt = 0; nt < 8; nt++) {
        int col = nt * 8 + 2 * c;
        *(float2*)(O + r0 + col) =
            make_float2(rnaf(acc[nt][0] * inv0), rnaf(acc[nt][1] * inv0));
        *(float2*)(O + r1 + col) =
            make_float2(rnaf(acc[nt][2] * inv1), rnaf(acc[nt][3] * inv1));
    }
}

// ---------------- launch ---------------------------------------------------
extern "C" void kernel_launch(void* const* d_in, const int* in_sizes, int n_in,
                              void* d_out, int out_size)
{
    const float* hidden = (const float*)d_in[0];
    const int*   mask   = (const int*)d_in[1];
    const float* wq = (const float*)d_in[2];
    const float* bq = (const float*)d_in[3];
    const float* wk = (const float*)d_in[4];
    const float* bk = (const float*)d_in[5];
    const float* wv = (const float*)d_in[6];
    const float* bv = (const float*)d_in[7];
    const float* wo = (const float*)d_in[8];
    const float* bo = (const float*)d_in[9];
    const float* w1 = (const float*)d_in[10];
    const float* b1 = (const float*)d_in[11];
    const float* w2 = (const float*)d_in[12];
    const float* b2 = (const float*)d_in[13];
    const float* ln1_g = (const float*)d_in[14];
    const float* ln1_b = (const float*)d_in[15];
    const float* ln2_g = (const float*)d_in[16];
    const float* ln2_b = (const float*)d_in[17];
    float* out = (float*)d_out;

    float *ln, *qkv, *attn, *h1, *f1, *wqkv, *bqkv, *wor, *w1r, *w2r;
    cudaGetSymbolAddress((void**)&ln,   g_ln);
    cudaGetSymbolAddress((void**)&qkv,  g_qkv);
    cudaGetSymbolAddress((void**)&attn, g_attn);
    cudaGetSymbolAddress((void**)&h1,   g_h1);
    cudaGetSymbolAddress((void**)&f1,   g_f1);
    cudaGetSymbolAddress((void**)&wqkv, g_wqkv);
    cudaGetSymbolAddress((void**)&bqkv, g_bqkv);
    cudaGetSymbolAddress((void**)&wor,  g_wor);
    cudaGetSymbolAddress((void**)&w1r,  g_w1r);
    cudaGetSymbolAddress((void**)&w2r,  g_w2r);

    cudaFuncSetAttribute(flash_tc,
                         cudaFuncAttributeMaxDynamicSharedMemorySize, FLASH_SMEM);
    cudaFuncSetAttribute(gemm_tf32<1>,
                         cudaFuncAttributeMaxDynamicSharedMemorySize, GEMM_SMEM);
    cudaFuncSetAttribute(gemm_tf32<2>,
                         cudaFuncAttributeMaxDynamicSharedMemorySize, GEMM_SMEM);
    cudaFuncSetAttribute(gemm_tf32<3>,
                         cudaFuncAttributeMaxDynamicSharedMemorySize, GEMM_SMEM);

    // pack weights (rna-rounded); QKV fused into one strided buffer
    int nblk = (DD * DD / 4 + 255) / 256;
    wround_qkv_kernel<<<nblk, 256>>>(wq, wqkv, 0);
    wround_qkv_kernel<<<nblk, 256>>>(wk, wqkv, DD);
    wround_qkv_kernel<<<nblk, 256>>>(wv, wqkv, 2 * DD);
    bpack_kernel<<<(DD + 255) / 256, 256>>>(bq, bk, bv, bqkv);
    wround_kernel<<<nblk, 256>>>(wo, wor, DD * DD / 4);
    wround_kernel<<<(DD * DFF / 4 + 255) / 256, 256>>>(w1, w1r, DD * DFF / 4);
    wround_kernel<<<(DFF * DD / 4 + 255) / 256, 256>>>(w2, w2r, DFF * DD / 4);

    // 1) LN1
    ln_kernel<<<NROWS, 256>>>(hidden, ln1_g, ln1_b, ln);

    // 2) fused QKV projection
    dim3 gQKV(NQKV / 128, NROWS / 128);
    gemm_tf32<3><<<gQKV, 256, GEMM_SMEM>>>(ln, wqkv, bqkv, nullptr, qkv,
                                           NROWS, DD, NQKV);

    // 3) attention
    flash_tc<<<dim3(SS / 128, HH, BB), 256, FLASH_SMEM>>>(
        qkv, qkv + DD, qkv + 2 * DD, NQKV, mask, attn);

    // 4) output projection + residual
    dim3 gD(DD / 128, NROWS / 128);
    gemm_tf32<2><<<gD, 256, GEMM_SMEM>>>(attn, wor, bo, hidden, h1, NROWS, DD, DD);

    // 5) LN2
    ln_kernel<<<NROWS, 256>>>(h1, ln2_g, ln2_b, ln);

    // 6) FFN
    dim3 gF(DFF / 128, NROWS / 128);
    gemm_tf32<1><<<gF, 256, GEMM_SMEM>>>(ln, w1r, b1, nullptr, f1, NROWS, DD, DFF);
    gemm_tf32<2><<<gD, 256, GEMM_SMEM>>>(f1, w2r, b2, h1, out, NROWS, DFF, DD);
}

// round 6
// speedup vs baseline: 6.1553x; 1.8299x over previous
#include <cuda_runtime.h>
#include <cuda_fp16.h>
#include <math.h>
#include <stdint.h>

#define BB 2
#define SS 2048
#define DD 1024
#define HH 16
#define DHD 64
#define DFF 4096
#define NROWS (BB * SS)
#define NQKV 3072

// ---------------- scratch (device globals; no allocation) ----------------
__device__ __half g_ln[NROWS * DD];
__device__ __half g_qkv[NROWS * NQKV];
__device__ __half g_attn[NROWS * DD];
__device__ float  g_h1[NROWS * DD];
__device__ __half g_f1[NROWS * DFF];
__device__ __half g_wqkv[DD * NQKV];
__device__ float  g_bqkv[NQKV];
__device__ __half g_wo[DD * DD];
__device__ __half g_w1[DD * DFF];
__device__ __half g_w2[DFF * DD];

// ---------------- helpers --------------------------------------------------
__device__ __forceinline__ uint32_t smem_u32(const void* p) {
    uint32_t a;
    asm("{ .reg .u64 t; cvta.to.shared.u64 t, %1; cvt.u32.u64 %0, t; }" : "=r"(a) : "l"(p));
    return a;
}
__device__ __forceinline__ void cp16(void* dst_smem, const void* src) {
    uint32_t d;
    asm("{ .reg .u64 t; cvta.to.shared.u64 t, %1; cvt.u32.u64 %0, t; }"
        : "=r"(d) : "l"(dst_smem));
    asm volatile("cp.async.cg.shared.global [%0], [%1], 16;" :: "r"(d), "l"(src));
}
__device__ __forceinline__ void cp_commit() {
    asm volatile("cp.async.commit_group;");
}
template <int N>
__device__ __forceinline__ void cp_wait() {
    asm volatile("cp.async.wait_group %0;" :: "n"(N));
}
__device__ __forceinline__ void ldm_x4(uint32_t r[4], uint32_t addr) {
    asm volatile("ldmatrix.sync.aligned.m8n8.x4.shared.b16 {%0,%1,%2,%3}, [%4];"
        : "=r"(r[0]), "=r"(r[1]), "=r"(r[2]), "=r"(r[3]) : "r"(addr));
}
__device__ __forceinline__ void ldm_x4t(uint32_t r[4], uint32_t addr) {
    asm volatile("ldmatrix.sync.aligned.m8n8.x4.trans.shared.b16 {%0,%1,%2,%3}, [%4];"
        : "=r"(r[0]), "=r"(r[1]), "=r"(r[2]), "=r"(r[3]) : "r"(addr));
}
__device__ __forceinline__ void mma16(float c[4], const uint32_t a[4], const uint32_t b[2]) {
    asm volatile(
        "mma.sync.aligned.m16n8k16.row.col.f32.f16.f16.f32 "
        "{%0,%1,%2,%3}, {%4,%5,%6,%7}, {%8,%9}, {%0,%1,%2,%3};"
        : "+f"(c[0]), "+f"(c[1]), "+f"(c[2]), "+f"(c[3])
        : "r"(a[0]), "r"(a[1]), "r"(a[2]), "r"(a[3]), "r"(b[0]), "r"(b[1]));
}
__device__ __forceinline__ uint32_t packh2(float lo, float hi) {
    __half2 h = __floats2half2_rn(lo, hi);
    return *(uint32_t*)&h;
}
__device__ __forceinline__ float gelu_tanh_f(float h) {
    const float c = 0.7978845608028654f;
    float u = c * (h + 0.044715f * h * h * h);
    return 0.5f * h * (1.0f + tanhf(u));
}

// ---------------- weight packs (fp32 -> fp16) -------------------------------
__global__ void __launch_bounds__(256) wpack_h(
    const float* __restrict__ in, __half* __restrict__ out, int n4)
{
    int i = blockIdx.x * 256 + threadIdx.x;
    if (i < n4) {
        float4 v = ((const float4*)in)[i];
        __half2* o = (__half2*)(out + (size_t)i * 4);
        o[0] = __floats2half2_rn(v.x, v.y);
        o[1] = __floats2half2_rn(v.z, v.w);
    }
}
// strided: in [1024 x 1024] -> out rows of 3072 at column offset
__global__ void __launch_bounds__(256) wpack_qkv(
    const float* __restrict__ in, __half* __restrict__ out, int coff)
{
    int i = blockIdx.x * 256 + threadIdx.x;  // over DD*DD/4
    int row = i >> 8, c4 = (i & 255) << 2;
    float4 v = ((const float4*)in)[i];
    __half2* o = (__half2*)(out + (size_t)row * NQKV + coff + c4);
    o[0] = __floats2half2_rn(v.x, v.y);
    o[1] = __floats2half2_rn(v.z, v.w);
}
__global__ void __launch_bounds__(256) bpack_kernel(
    const float* __restrict__ bq, const float* __restrict__ bk,
    const float* __restrict__ bv, float* __restrict__ out)
{
    int i = blockIdx.x * 256 + threadIdx.x;
    if (i < DD) {
        out[i] = bq[i];
        out[DD + i] = bk[i];
        out[2 * DD + i] = bv[i];
    }
}

// ---------------- LayerNorm (Bessel var, eps on std) -> fp16 out ------------
__global__ void __launch_bounds__(256) ln_kernel(
    const float* __restrict__ x, const float* __restrict__ gw,
    const float* __restrict__ bw, __half* __restrict__ y)
{
    int row = blockIdx.x;
    int t = threadIdx.x;
    const float4* xr = (const float4*)(x + (size_t)row * DD);
    float4 v = xr[t];
    float s  = v.x + v.y + v.z + v.w;
    float ss = v.x * v.x + v.y * v.y + v.z * v.z + v.w * v.w;

    __shared__ float rs[8], rss[8];
    #pragma unroll
    for (int o = 16; o; o >>= 1) {
        s  += __shfl_xor_sync(0xffffffffu, s,  o);
        ss += __shfl_xor_sync(0xffffffffu, ss, o);
    }
    if ((t & 31) == 0) { rs[t >> 5] = s; rss[t >> 5] = ss; }
    __syncthreads();
    __shared__ float mean_s, rd_s;
    if (t == 0) {
        float S = 0.f, SQ = 0.f;
        #pragma unroll
        for (int i = 0; i < 8; i++) { S += rs[i]; SQ += rss[i]; }
        float mean = S * (1.0f / DD);
        float var  = (SQ - S * S * (1.0f / DD)) * (1.0f / (DD - 1));
        var = fmaxf(var, 0.f);
        mean_s = mean;
        rd_s = 1.0f / (sqrtf(var) + 1e-6f);
    }
    __syncthreads();
    float mean = mean_s, rd = rd_s;
    float4 g4 = ((const float4*)gw)[t];
    float4 b4 = ((const float4*)bw)[t];
    __half2* o = (__half2*)(y + (size_t)row * DD + t * 4);
    o[0] = __floats2half2_rn(g4.x * (v.x - mean) * rd + b4.x,
                             g4.y * (v.y - mean) * rd + b4.y);
    o[1] = __floats2half2_rn(g4.z * (v.z - mean) * rd + b4.z,
                             g4.w * (v.w - mean) * rd + b4.w);
}

// ---------------- fp16 mma GEMM (128x128x32, 8 warps, 2 CTA/SM) -------------
#define TKH 32
#define ASTRH 40
#define BSTRH 136
#define A_TILE_H (128 * ASTRH)
#define B_TILE_H (TKH * BSTRH)
#define STAGE_H (A_TILE_H + B_TILE_H)
#define NSTG 3
#define GEMM_SMEM (NSTG * STAGE_H * 2)

// EPI: 1 = bias+gelu -> fp16 out, 2 = bias+residual -> fp32 out,
//      3 = bias -> fp16 out
template <int EPI>
__global__ void __launch_bounds__(256, 2) gemm_f16(
    const __half* __restrict__ A, const __half* __restrict__ W,
    const float* __restrict__ bias, const float* __restrict__ R,
    void* __restrict__ Cv, int M, int K, int N)
{
    extern __shared__ __half smh[];
    uint32_t sbase = smem_u32(smh);
    int t = threadIdx.x;
    int m0 = blockIdx.y * 128, n0 = blockIdx.x * 128;
    int nkt = K >> 5;

    auto load_tile = [&](int stg, int kt) {
        __half* As = smh + stg * STAGE_H;
        __half* Bs = As + A_TILE_H;
        int k0 = kt * TKH;
        #pragma unroll
        for (int i = 0; i < 2; i++) {
            int id = t + i * 256;
            int row = id >> 2, c8 = (id & 3) << 3;
            cp16(As + row * ASTRH + c8, A + (size_t)(m0 + row) * K + k0 + c8);
        }
        #pragma unroll
        for (int i = 0; i < 2; i++) {
            int id = t + i * 256;
            int row = id >> 4, c8 = (id & 15) << 3;
            cp16(Bs + row * BSTRH + c8, W + (size_t)(k0 + row) * N + n0 + c8);
        }
    };

    float acc[4][4][4];
    #pragma unroll
    for (int mt = 0; mt < 4; mt++)
        #pragma unroll
        for (int nt = 0; nt < 4; nt++)
            #pragma unroll
            for (int i = 0; i < 4; i++) acc[mt][nt][i] = 0.f;

    int lane = t & 31, wid = t >> 5;
    int warpM = wid >> 2, warpN = wid & 3;
    int g = lane >> 2, c = lane & 3;
    int arow_l = lane & 15;
    int acol_l = (lane >> 4) << 3;
    int mat = lane >> 3, lr = lane & 7;
    int bko = ((mat & 1) << 3) + lr;        // k offset within 16-chunk
    int bno = (mat >> 1) << 3;              // n offset within 16-pair

    #pragma unroll
    for (int s = 0; s < NSTG; s++) { load_tile(s, s); cp_commit(); }

    for (int kt = 0; kt < nkt; kt++) {
        cp_wait<NSTG - 1>();
        __syncthreads();

        uint32_t As_u = sbase + (uint32_t)((kt % NSTG) * STAGE_H) * 2;
        uint32_t Bs_u = As_u + A_TILE_H * 2;

        #pragma unroll
        for (int ks = 0; ks < 2; ks++) {
            uint32_t af[4][4];
            #pragma unroll
            for (int mt = 0; mt < 4; mt++)
                ldm_x4(af[mt], As_u +
                    ((uint32_t)((warpM * 64 + mt * 16 + arow_l) * ASTRH
                                + ks * 16 + acol_l) << 1));
            uint32_t b4[2][4];
            #pragma unroll
            for (int p = 0; p < 2; p++) {
                int bk = ks * 16 + bko;
                int bn = warpN * 32 + p * 16 + bno;
                ldm_x4t(b4[p], Bs_u + ((uint32_t)(bk * BSTRH + bn) << 1));
            }
            #pragma unroll
            for (int mt = 0; mt < 4; mt++)
                #pragma unroll
                for (int nt = 0; nt < 4; nt++)
                    mma16(acc[mt][nt], af[mt], &b4[nt >> 1][(nt & 1) << 1]);
        }

        __syncthreads();
        int nx = kt + NSTG;
        if (nx < nkt) load_tile(kt % NSTG, nx);
        cp_commit();
    }

    int rbase = m0 + warpM * 64 + g;
    int cbase = n0 + warpN * 32 + 2 * c;

    #pragma unroll
    for (int nt = 0; nt < 4; nt++) {
        int col = cbase + nt * 8;
        float2 b2 = *(const float2*)(bias + col);
        #pragma unroll
        for (int mt = 0; mt < 4; mt++) {
            int r0 = rbase + mt * 16;
            float v0x = acc[mt][nt][0] + b2.x;
            float v0y = acc[mt][nt][1] + b2.y;
            float v1x = acc[mt][nt][2] + b2.x;
            float v1y = acc[mt][nt][3] + b2.y;
            if (EPI == 2) {
                float* C = (float*)Cv;
                float2 r0v = *(const float2*)(R + (size_t)r0 * N + col);
                float2 r1v = *(const float2*)(R + (size_t)(r0 + 8) * N + col);
                *(float2*)(C + (size_t)r0 * N + col) =
                    make_float2(v0x + r0v.x, v0y + r0v.y);
                *(float2*)(C + (size_t)(r0 + 8) * N + col) =
                    make_float2(v1x + r1v.x, v1y + r1v.y);
            } else {
                if (EPI == 1) {
                    v0x = gelu_tanh_f(v0x); v0y = gelu_tanh_f(v0y);
                    v1x = gelu_tanh_f(v1x); v1y = gelu_tanh_f(v1y);
                }
                __half* C = (__half*)Cv;
                *(__half2*)(C + (size_t)r0 * N + col) = __floats2half2_rn(v0x, v0y);
                *(__half2*)(C + (size_t)(r0 + 8) * N + col) = __floats2half2_rn(v1x, v1y);
            }
        }
    }
}

// ---------------- fp16 tensor-core flash attention ---------------------------
#define FQSTR 72
#define FQ_H (128 * FQSTR)
#define FKV_H (64 * FQSTR)
#define KOFF FQ_H
#define VOFF (FQ_H + 2 * FKV_H)
#define MOFF_BYTES ((FQ_H + 4 * FKV_H) * 2)
#define FLASH_SMEM (MOFF_BYTES + 2 * 64 * 4 + 16)

__global__ void __launch_bounds__(256, 2) flash_f16(
    const __half* __restrict__ Q, const __half* __restrict__ Kg,
    const __half* __restrict__ Vg, int ldq, const int* __restrict__ mask,
    __half* __restrict__ O)
{
    extern __shared__ __half smh[];
    uint32_t sbase = smem_u32(smh);
    int* mksm = (int*)((char*)smh + MOFF_BYTES);
    int t = threadIdx.x;
    int lane = t & 31, wid = t >> 5;
    int g = lane >> 2, c = lane & 3;
    int q0 = blockIdx.x * 128;
    int h = blockIdx.y, b = blockIdx.z;
    size_t baseQ = ((size_t)(b * SS + q0)) * ldq + h * DHD;

    auto load_kv = [&](int kt, int s) {
        size_t baseK = ((size_t)(b * SS + kt * 64)) * ldq + h * DHD;
        __half* Kb = smh + KOFF + s * FKV_H;
        __half* Vb = smh + VOFF + s * FKV_H;
        #pragma unroll
        for (int i = 0; i < 2; i++) {
            int id = t + i * 256;
            int row = id >> 3, c8 = (id & 7) << 3;
            cp16(Kb + row * FQSTR + c8, Kg + baseK + (size_t)row * ldq + c8);
            cp16(Vb + row * FQSTR + c8, Vg + baseK + (size_t)row * ldq + c8);
        }
        if (t < 16) cp16(mksm + s * 64 + t * 4, mask + b * SS + kt * 64 + t * 4);
    };

    load_kv(0, 0);
    cp_commit();
    #pragma unroll
    for (int i = 0; i < 4; i++) {
        int id = t + i * 256;
        int row = id >> 3, c8 = (id & 7) << 3;
        cp16(smh + row * FQSTR + c8, Q + baseQ + (size_t)row * ldq + c8);
    }
    cp_commit();
    load_kv(1, 1);
    cp_commit();

    cp_wait<1>();
    __syncthreads();

    // Q fragments (raw fp16; 1/8 scale applied in fp32 after S-mma)
    int arow_l = lane & 15;
    int acol_l = (lane >> 4) << 3;
    int mat = lane >> 3, lr = lane & 7;
    uint32_t qf[4][4];
    int qb = wid * 16;
    #pragma unroll
    for (int ks = 0; ks < 4; ks++)
        ldm_x4(qf[ks], sbase +
            ((uint32_t)((qb + arow_l) * FQSTR + ks * 16 + acol_l) << 1));

    float m0 = -1e30f, m1 = -1e30f, l0 = 0.f, l1 = 0.f;
    float acc[8][4];
    #pragma unroll
    for (int nt = 0; nt < 8; nt++)
        #pragma unroll
        for (int i = 0; i < 4; i++) acc[nt][i] = 0.f;

    for (int kt = 0; kt < SS / 64; kt++) {
        cp_wait<1>();
        __syncthreads();
        uint32_t Ku = sbase + (uint32_t)((KOFF + (kt & 1) * FKV_H) * 2);
        uint32_t Vu = sbase + (uint32_t)((VOFF + (kt & 1) * FKV_H) * 2);
        const int* mk = mksm + (kt & 1) * 64;

        // S = Q K^T
        float sf[8][4];
        #pragma unroll
        for (int nt = 0; nt < 8; nt++)
            #pragma unroll
            for (int i = 0; i < 4; i++) sf[nt][i] = 0.f;

        #pragma unroll
        for (int ks = 0; ks < 4; ks++) {
            int kk = ks * 16 + ((mat & 1) << 3);
            #pragma unroll
            for (int p = 0; p < 4; p++) {
                int kn = p * 16 + ((mat >> 1) << 3) + lr;
                uint32_t kb[4];
                ldm_x4(kb, Ku + ((uint32_t)(kn * FQSTR + kk) << 1));
                mma16(sf[2 * p],     qf[ks], kb);
                mma16(sf[2 * p + 1], qf[ks], kb + 2);
            }
        }

        // scale + mask bias + online softmax (rows g, g+8; warp-local)
        float mx0 = -1e30f, mx1 = -1e30f;
        #pragma unroll
        for (int nt = 0; nt < 8; nt++) {
            float bia0 = mk[nt * 8 + 2 * c]     ? 0.f : -1e9f;
            float bia1 = mk[nt * 8 + 2 * c + 1] ? 0.f : -1e9f;
            sf[nt][0] = sf[nt][0] * 0.125f + bia0;
            sf[nt][1] = sf[nt][1] * 0.125f + bia1;
            sf[nt][2] = sf[nt][2] * 0.125f + bia0;
            sf[nt][3] = sf[nt][3] * 0.125f + bia1;
            mx0 = fmaxf(mx0, fmaxf(sf[nt][0], sf[nt][1]));
            mx1 = fmaxf(mx1, fmaxf(sf[nt][2], sf[nt][3]));
        }
        mx0 = fmaxf(mx0, __shfl_xor_sync(0xffffffffu, mx0, 1));
        mx0 = fmaxf(mx0, __shfl_xor_sync(0xffffffffu, mx0, 2));
        mx1 = fmaxf(mx1, __shfl_xor_sync(0xffffffffu, mx1, 1));
        mx1 = fmaxf(mx1, __shfl_xor_sync(0xffffffffu, mx1, 2));

        float mn0 = fmaxf(m0, mx0), mn1 = fmaxf(m1, mx1);
        float al0 = __expf(m0 - mn0), al1 = __expf(m1 - mn1);
        m0 = mn0; m1 = mn1;

        float ps0 = 0.f, ps1 = 0.f;
        #pragma unroll
        for (int nt = 0; nt < 8; nt++) {
            sf[nt][0] = __expf(sf[nt][0] - mn0);
            sf[nt][1] = __expf(sf[nt][1] - mn0);
            sf[nt][2] = __expf(sf[nt][2] - mn1);
            sf[nt][3] = __expf(sf[nt][3] - mn1);
            ps0 += sf[nt][0] + sf[nt][1];
            ps1 += sf[nt][2] + sf[nt][3];
        }
        ps0 += __shfl_xor_sync(0xffffffffu, ps0, 1);
        ps0 += __shfl_xor_sync(0xffffffffu, ps0, 2);
        ps1 += __shfl_xor_sync(0xffffffffu, ps1, 1);
        ps1 += __shfl_xor_sync(0xffffffffu, ps1, 2);
        l0 = l0 * al0 + ps0;
        l1 = l1 * al1 + ps1;

        #pragma unroll
        for (int nt = 0; nt < 8; nt++) {
            acc[nt][0] *= al0; acc[nt][1] *= al0;
            acc[nt][2] *= al1; acc[nt][3] *= al1;
        }

        // acc += P V  (P packed straight from registers)
        #pragma unroll
        for (int ks = 0; ks < 4; ks++) {
            uint32_t af[4];
            af[0] = packh2(sf[2 * ks][0],     sf[2 * ks][1]);
            af[1] = packh2(sf[2 * ks][2],     sf[2 * ks][3]);
            af[2] = packh2(sf[2 * ks + 1][0], sf[2 * ks + 1][1]);
            af[3] = packh2(sf[2 * ks + 1][2], sf[2 * ks + 1][3]);
            int vk = ks * 16 + ((mat & 1) << 3) + lr;
            #pragma unroll
            for (int p = 0; p < 4; p++) {
                int vn = p * 16 + ((mat >> 1) << 3);
                uint32_t vb[4];
                ldm_x4t(vb, Vu + ((uint32_t)(vk * FQSTR + vn) << 1));
                mma16(acc[2 * p],     af, vb);
                mma16(acc[2 * p + 1], af, vb + 2);
            }
        }

        __syncthreads();
        if (kt + 2 < SS / 64) load_kv(kt + 2, kt & 1);
        cp_commit();
    }

    float inv0 = 1.f / l0, inv1 = 1.f / l1;
    size_t r0 = ((size_t)(b * SS + q0 + qb + g)) * DD + h * DHD;
    size_t r1 = r0 + 8 * DD;
    #pragma unroll
    for (int nt = 0; nt < 8; nt++) {
        int col = nt * 8 + 2 * c;
        *(__half2*)(O + r0 + col) =
            __floats2half2_rn(acc[nt][0] * inv0, acc[nt][1] * inv0);
        *(__half2*)(O + r1 + col) =
            __floats2half2_rn(acc[nt][2] * inv1, acc[nt][3] * inv1);
    }
}

// ---------------- launch ---------------------------------------------------
extern "C" void kernel_launch(void* const* d_in, const int* in_sizes, int n_in,
                              void* d_out, int out_size)
{
    const float* hidden = (const float*)d_in[0];
    const int*   mask   = (const int*)d_in[1];
    const float* wq = (const float*)d_in[2];
    const float* bq = (const float*)d_in[3];
    const float* wk = (const float*)d_in[4];
    const float* bk = (const float*)d_in[5];
    const float* wv = (const float*)d_in[6];
    const float* bv = (const float*)d_in[7];
    const float* wo = (const float*)d_in[8];
    const float* bo = (const float*)d_in[9];
    const float* w1 = (const float*)d_in[10];
    const float* b1 = (const float*)d_in[11];
    const float* w2 = (const float*)d_in[12];
    const float* b2 = (const float*)d_in[13];
    const float* ln1_g = (const float*)d_in[14];
    const float* ln1_b = (const float*)d_in[15];
    const float* ln2_g = (const float*)d_in[16];
    const float* ln2_b = (const float*)d_in[17];
    float* out = (float*)d_out;

    __half *ln, *qkv, *attn, *f1, *wqkvh, *woh, *w1h, *w2h;
    float *h1, *bqkv;
    cudaGetSymbolAddress((void**)&ln,    g_ln);
    cudaGetSymbolAddress((void**)&qkv,   g_qkv);
    cudaGetSymbolAddress((void**)&attn,  g_attn);
    cudaGetSymbolAddress((void**)&h1,    g_h1);
    cudaGetSymbolAddress((void**)&f1,    g_f1);
    cudaGetSymbolAddress((void**)&wqkvh, g_wqkv);
    cudaGetSymbolAddress((void**)&bqkv,  g_bqkv);
    cudaGetSymbolAddress((void**)&woh,   g_wo);
    cudaGetSymbolAddress((void**)&w1h,   g_w1);
    cudaGetSymbolAddress((void**)&w2h,   g_w2);

    cudaFuncSetAttribute(flash_f16,
                         cudaFuncAttributeMaxDynamicSharedMemorySize, FLASH_SMEM);
    cudaFuncSetAttribute(gemm_f16<1>,
                         cudaFuncAttributeMaxDynamicSharedMemorySize, GEMM_SMEM);
    cudaFuncSetAttribute(gemm_f16<2>,
                         cudaFuncAttributeMaxDynamicSharedMemorySize, GEMM_SMEM);
    cudaFuncSetAttribute(gemm_f16<3>,
                         cudaFuncAttributeMaxDynamicSharedMemorySize, GEMM_SMEM);

    // pack weights to fp16 (QKV fused into one strided buffer)
    int nblk = (DD * DD / 4 + 255) / 256;
    wpack_qkv<<<nblk, 256>>>(wq, wqkvh, 0);
    wpack_qkv<<<nblk, 256>>>(wk, wqkvh, DD);
    wpack_qkv<<<nblk, 256>>>(wv, wqkvh, 2 * DD);
    bpack_kernel<<<(DD + 255) / 256, 256>>>(bq, bk, bv, bqkv);
    wpack_h<<<nblk, 256>>>(wo, woh, DD * DD / 4);
    wpack_h<<<(DD * DFF / 4 + 255) / 256, 256>>>(w1, w1h, DD * DFF / 4);
    wpack_h<<<(DFF * DD / 4 + 255) / 256, 256>>>(w2, w2h, DFF * DD / 4);

    // 1) LN1
    ln_kernel<<<NROWS, 256>>>(hidden, ln1_g, ln1_b, ln);

    // 2) fused QKV projection -> fp16
    dim3 gQKV(NQKV / 128, NROWS / 128);
    gemm_f16<3><<<gQKV, 256, GEMM_SMEM>>>(ln, wqkvh, bqkv, nullptr, qkv,
                                          NROWS, DD, NQKV);

    // 3) attention (fp16 tensor flash) -> fp16
    flash_f16<<<dim3(SS / 128, HH, BB), 256, FLASH_SMEM>>>(
        qkv, qkv + DD, qkv + 2 * DD, NQKV, mask, attn);

    // 4) output projection + residual -> fp32
    dim3 gD(DD / 128, NROWS / 128);
    gemm_f16<2><<<gD, 256, GEMM_SMEM>>>(attn, woh, bo, hidden, h1, NROWS, DD, DD);

    // 5) LN2
    ln_kernel<<<NROWS, 256>>>(h1, ln2_g, ln2_b, ln);

    // 6) FFN
    dim3 gF(DFF / 128, NROWS / 128);
    gemm_f16<1><<<gF, 256, GEMM_SMEM>>>(ln, w1h, b1, nullptr, f1, NROWS, DD, DFF);
    gemm_f16<2><<<gD, 256, GEMM_SMEM>>>(f1, w2h, b2, h1, out, NROWS, DFF, DD);
}

// round 7
// speedup vs baseline: 6.5440x; 1.0632x over previous
#include <cuda_runtime.h>
#include <cuda_fp16.h>
#include <math.h>
#include <stdint.h>

#define BB 2
#define SS 2048
#define DD 1024
#define HH 16
#define DHD 64
#define DFF 4096
#define NROWS (BB * SS)
#define NQKV 3072

// ---------------- scratch (device globals; no allocation) ----------------
__device__ __half g_ln[NROWS * DD];
__device__ __half g_qkv[NROWS * NQKV];
__device__ __half g_attn[NROWS * DD];
__device__ float  g_h1[NROWS * DD];
__device__ __half g_f1[NROWS * DFF];
__device__ __half g_wqkv[DD * NQKV];
__device__ float  g_bqkv[NQKV];
__device__ __half g_wo[DD * DD];
__device__ __half g_w1[DD * DFF];
__device__ __half g_w2[DFF * DD];

// ---------------- helpers --------------------------------------------------
__device__ __forceinline__ uint32_t smem_u32(const void* p) {
    uint32_t a;
    asm("{ .reg .u64 t; cvta.to.shared.u64 t, %1; cvt.u32.u64 %0, t; }" : "=r"(a) : "l"(p));
    return a;
}
__device__ __forceinline__ void cp16(void* dst_smem, const void* src) {
    uint32_t d;
    asm("{ .reg .u64 t; cvta.to.shared.u64 t, %1; cvt.u32.u64 %0, t; }"
        : "=r"(d) : "l"(dst_smem));
    asm volatile("cp.async.cg.shared.global [%0], [%1], 16;" :: "r"(d), "l"(src));
}
__device__ __forceinline__ void cp_commit() {
    asm volatile("cp.async.commit_group;");
}
template <int N>
__device__ __forceinline__ void cp_wait() {
    asm volatile("cp.async.wait_group %0;" :: "n"(N));
}
__device__ __forceinline__ void ldm_x4(uint32_t r[4], uint32_t addr) {
    asm volatile("ldmatrix.sync.aligned.m8n8.x4.shared.b16 {%0,%1,%2,%3}, [%4];"
        : "=r"(r[0]), "=r"(r[1]), "=r"(r[2]), "=r"(r[3]) : "r"(addr));
}
__device__ __forceinline__ void ldm_x4t(uint32_t r[4], uint32_t addr) {
    asm volatile("ldmatrix.sync.aligned.m8n8.x4.trans.shared.b16 {%0,%1,%2,%3}, [%4];"
        : "=r"(r[0]), "=r"(r[1]), "=r"(r[2]), "=r"(r[3]) : "r"(addr));
}
__device__ __forceinline__ void mma16(float c[4], const uint32_t a[4], const uint32_t b[2]) {
    asm volatile(
        "mma.sync.aligned.m16n8k16.row.col.f32.f16.f16.f32 "
        "{%0,%1,%2,%3}, {%4,%5,%6,%7}, {%8,%9}, {%0,%1,%2,%3};"
        : "+f"(c[0]), "+f"(c[1]), "+f"(c[2]), "+f"(c[3])
        : "r"(a[0]), "r"(a[1]), "r"(a[2]), "r"(a[3]), "r"(b[0]), "r"(b[1]));
}
__device__ __forceinline__ uint32_t packh2(float lo, float hi) {
    __half2 h = __floats2half2_rn(lo, hi);
    return *(uint32_t*)&h;
}
__device__ __forceinline__ float gelu_tanh_f(float h) {
    const float c = 0.7978845608028654f;
    float u = c * (h + 0.044715f * h * h * h);
    return 0.5f * h * (1.0f + tanhf(u));
}

// ---------------- ONE fused pack kernel (all weights + biases) -------------
#define NW (DD * DD / 4)
#define NF (DD * DFF / 4)
__global__ void __launch_bounds__(256) pack_all(
    const float* __restrict__ wq, const float* __restrict__ wk,
    const float* __restrict__ wv, const float* __restrict__ wo,
    const float* __restrict__ w1, const float* __restrict__ w2,
    const float* __restrict__ bq, const float* __restrict__ bk,
    const float* __restrict__ bv,
    __half* __restrict__ wqkv, __half* __restrict__ woh,
    __half* __restrict__ w1h, __half* __restrict__ w2h,
    float* __restrict__ bqkv)
{
    long i = (long)blockIdx.x * 256 + threadIdx.x;
    if (i < 3L * NW) {
        const float* src = (i < NW) ? wq : (i < 2L * NW) ? wk : wv;
        int coff = (i < NW) ? 0 : (i < 2L * NW) ? DD : 2 * DD;
        long ii = i % NW;
        int row = (int)(ii >> 8), c4 = ((int)ii & 255) << 2;
        float4 v = ((const float4*)src)[ii];
        __half2* o = (__half2*)(wqkv + (size_t)row * NQKV + coff + c4);
        o[0] = __floats2half2_rn(v.x, v.y);
        o[1] = __floats2half2_rn(v.z, v.w);
    } else if (i < 4L * NW) {
        long ii = i - 3L * NW;
        float4 v = ((const float4*)wo)[ii];
        __half2* o = (__half2*)(woh + ii * 4);
        o[0] = __floats2half2_rn(v.x, v.y);
        o[1] = __floats2half2_rn(v.z, v.w);
    } else if (i < 4L * NW + NF) {
        long ii = i - 4L * NW;
        float4 v = ((const float4*)w1)[ii];
        __half2* o = (__half2*)(w1h + ii * 4);
        o[0] = __floats2half2_rn(v.x, v.y);
        o[1] = __floats2half2_rn(v.z, v.w);
    } else if (i < 4L * NW + 2L * NF) {
        long ii = i - 4L * NW - NF;
        float4 v = ((const float4*)w2)[ii];
        __half2* o = (__half2*)(w2h + ii * 4);
        o[0] = __floats2half2_rn(v.x, v.y);
        o[1] = __floats2half2_rn(v.z, v.w);
    } else {
        long ii = i - 4L * NW - 2L * NF;   // 0..767, each 4 floats
        if (ii < 768) {
            int j = (int)ii * 4;
            const float* src = (j < DD) ? bq : (j < 2 * DD) ? bk : bv;
            int jj = j & (DD - 1);
            *(float4*)(bqkv + j) = *(const float4*)(src + jj);
        }
    }
}
#define PACK_BLOCKS ((4L * NW + 2L * NF + 768 + 255) / 256)

// ---------------- LayerNorm (Bessel var, eps on std) -> fp16 out ------------
__global__ void __launch_bounds__(256) ln_kernel(
    const float* __restrict__ x, const float* __restrict__ gw,
    const float* __restrict__ bw, __half* __restrict__ y)
{
    int row = blockIdx.x;
    int t = threadIdx.x;
    const float4* xr = (const float4*)(x + (size_t)row * DD);
    float4 v = xr[t];
    float s  = v.x + v.y + v.z + v.w;
    float ss = v.x * v.x + v.y * v.y + v.z * v.z + v.w * v.w;

    __shared__ float rs[8], rss[8];
    #pragma unroll
    for (int o = 16; o; o >>= 1) {
        s  += __shfl_xor_sync(0xffffffffu, s,  o);
        ss += __shfl_xor_sync(0xffffffffu, ss, o);
    }
    if ((t & 31) == 0) { rs[t >> 5] = s; rss[t >> 5] = ss; }
    __syncthreads();
    __shared__ float mean_s, rd_s;
    if (t == 0) {
        float S = 0.f, SQ = 0.f;
        #pragma unroll
        for (int i = 0; i < 8; i++) { S += rs[i]; SQ += rss[i]; }
        float mean = S * (1.0f / DD);
        float var  = (SQ - S * S * (1.0f / DD)) * (1.0f / (DD - 1));
        var = fmaxf(var, 0.f);
        mean_s = mean;
        rd_s = 1.0f / (sqrtf(var) + 1e-6f);
    }
    __syncthreads();
    float mean = mean_s, rd = rd_s;
    float4 g4 = ((const float4*)gw)[t];
    float4 b4 = ((const float4*)bw)[t];
    __half2* o = (__half2*)(y + (size_t)row * DD + t * 4);
    o[0] = __floats2half2_rn(g4.x * (v.x - mean) * rd + b4.x,
                             g4.y * (v.y - mean) * rd + b4.y);
    o[1] = __floats2half2_rn(g4.z * (v.z - mean) * rd + b4.z,
                             g4.w * (v.w - mean) * rd + b4.w);
}

// ---------------- fp16 mma GEMM (128x128x32, 8 warps, 2 CTA/SM) -------------
// 4-stage cp.async pipeline, ONE __syncthreads per k-iteration.
#define TKH 32
#define ASTRH 40
#define BSTRH 136
#define A_TILE_H (128 * ASTRH)
#define B_TILE_H (TKH * BSTRH)
#define STAGE_H (A_TILE_H + B_TILE_H)
#define NSTG 4
#define GEMM_SMEM (NSTG * STAGE_H * 2)

// EPI: 1 = bias+gelu -> fp16 out, 2 = bias+residual -> fp32 out,
//      3 = bias -> fp16 out
template <int EPI>
__global__ void __launch_bounds__(256, 2) gemm_f16(
    const __half* __restrict__ A, const __half* __restrict__ W,
    const float* __restrict__ bias, const float* __restrict__ R,
    void* __restrict__ Cv, int M, int K, int N)
{
    extern __shared__ __half smh[];
    uint32_t sbase = smem_u32(smh);
    int t = threadIdx.x;
    int m0 = blockIdx.y * 128, n0 = blockIdx.x * 128;
    int nkt = K >> 5;

    auto load_tile = [&](int stg, int kt) {
        __half* As = smh + stg * STAGE_H;
        __half* Bs = As + A_TILE_H;
        int k0 = kt * TKH;
        #pragma unroll
        for (int i = 0; i < 2; i++) {
            int id = t + i * 256;
            int row = id >> 2, c8 = (id & 3) << 3;
            cp16(As + row * ASTRH + c8, A + (size_t)(m0 + row) * K + k0 + c8);
        }
        #pragma unroll
        for (int i = 0; i < 2; i++) {
            int id = t + i * 256;
            int row = id >> 4, c8 = (id & 15) << 3;
            cp16(Bs + row * BSTRH + c8, W + (size_t)(k0 + row) * N + n0 + c8);
        }
    };

    float acc[4][4][4];
    #pragma unroll
    for (int mt = 0; mt < 4; mt++)
        #pragma unroll
        for (int nt = 0; nt < 4; nt++)
            #pragma unroll
            for (int i = 0; i < 4; i++) acc[mt][nt][i] = 0.f;

    int lane = t & 31, wid = t >> 5;
    int warpM = wid >> 2, warpN = wid & 3;
    int g = lane >> 2, c = lane & 3;
    int arow_l = lane & 15;
    int acol_l = (lane >> 4) << 3;
    int mat = lane >> 3, lr = lane & 7;
    int bko = ((mat & 1) << 3) + lr;
    int bno = (mat >> 1) << 3;

    // prologue: NSTG-1 tiles in flight
    #pragma unroll
    for (int s = 0; s < NSTG - 1; s++) { load_tile(s, s); cp_commit(); }

    for (int kt = 0; kt < nkt; kt++) {
        cp_wait<NSTG - 2>();
        __syncthreads();

        // issue next tile into the stage consumed LAST iteration
        int nx = kt + NSTG - 1;
        if (nx < nkt) load_tile(nx & (NSTG - 1), nx);
        cp_commit();

        uint32_t As_u = sbase + (uint32_t)((kt & (NSTG - 1)) * STAGE_H) * 2;
        uint32_t Bs_u = As_u + A_TILE_H * 2;

        #pragma unroll
        for (int ks = 0; ks < 2; ks++) {
            uint32_t af[4][4];
            #pragma unroll
            for (int mt = 0; mt < 4; mt++)
                ldm_x4(af[mt], As_u +
                    ((uint32_t)((warpM * 64 + mt * 16 + arow_l) * ASTRH
                                + ks * 16 + acol_l) << 1));
            uint32_t b4[2][4];
            #pragma unroll
            for (int p = 0; p < 2; p++) {
                int bk = ks * 16 + bko;
                int bn = warpN * 32 + p * 16 + bno;
                ldm_x4t(b4[p], Bs_u + ((uint32_t)(bk * BSTRH + bn) << 1));
            }
            #pragma unroll
            for (int mt = 0; mt < 4; mt++)
                #pragma unroll
                for (int nt = 0; nt < 4; nt++)
                    mma16(acc[mt][nt], af[mt], &b4[nt >> 1][(nt & 1) << 1]);
        }
    }

    int rbase = m0 + warpM * 64 + g;
    int cbase = n0 + warpN * 32 + 2 * c;

    #pragma unroll
    for (int nt = 0; nt < 4; nt++) {
        int col = cbase + nt * 8;
        float2 b2 = *(const float2*)(bias + col);
        #pragma unroll
        for (int mt = 0; mt < 4; mt++) {
            int r0 = rbase + mt * 16;
            float v0x = acc[mt][nt][0] + b2.x;
            float v0y = acc[mt][nt][1] + b2.y;
            float v1x = acc[mt][nt][2] + b2.x;
            float v1y = acc[mt][nt][3] + b2.y;
            if (EPI == 2) {
                float* C = (float*)Cv;
                float2 r0v = *(const float2*)(R + (size_t)r0 * N + col);
                float2 r1v = *(const float2*)(R + (size_t)(r0 + 8) * N + col);
                *(float2*)(C + (size_t)r0 * N + col) =
                    make_float2(v0x + r0v.x, v0y + r0v.y);
                *(float2*)(C + (size_t)(r0 + 8) * N + col) =
                    make_float2(v1x + r1v.x, v1y + r1v.y);
            } else {
                if (EPI == 1) {
                    v0x = gelu_tanh_f(v0x); v0y = gelu_tanh_f(v0y);
                    v1x = gelu_tanh_f(v1x); v1y = gelu_tanh_f(v1y);
                }
                __half* C = (__half*)Cv;
                *(__half2*)(C + (size_t)r0 * N + col) = __floats2half2_rn(v0x, v0y);
                *(__half2*)(C + (size_t)(r0 + 8) * N + col) = __floats2half2_rn(v1x, v1y);
            }
        }
    }
}

// ---------------- fp16 tensor-core flash attention ---------------------------
// 3-stage KV pipeline, single sync per iteration.
#define FQSTR 72
#define FQ_H (128 * FQSTR)
#define FKV_H (64 * FQSTR)
#define KOFF FQ_H
#define VOFF (FQ_H + 3 * FKV_H)
#define MOFF_BYTES ((FQ_H + 6 * FKV_H) * 2)
#define FLASH_SMEM (MOFF_BYTES + 3 * 64 * 4 + 16)

__global__ void __launch_bounds__(256, 2) flash_f16(
    const __half* __restrict__ Q, const __half* __restrict__ Kg,
    const __half* __restrict__ Vg, int ldq, const int* __restrict__ mask,
    __half* __restrict__ O)
{
    extern __shared__ __half smh[];
    uint32_t sbase = smem_u32(smh);
    int* mksm = (int*)((char*)smh + MOFF_BYTES);
    int t = threadIdx.x;
    int lane = t & 31, wid = t >> 5;
    int g = lane >> 2, c = lane & 3;
    int q0 = blockIdx.x * 128;
    int h = blockIdx.y, b = blockIdx.z;
    size_t baseQ = ((size_t)(b * SS + q0)) * ldq + h * DHD;

    auto load_kv = [&](int kt, int s) {
        size_t baseK = ((size_t)(b * SS + kt * 64)) * ldq + h * DHD;
        __half* Kb = smh + KOFF + s * FKV_H;
        __half* Vb = smh + VOFF + s * FKV_H;
        #pragma unroll
        for (int i = 0; i < 2; i++) {
            int id = t + i * 256;
            int row = id >> 3, c8 = (id & 7) << 3;
            cp16(Kb + row * FQSTR + c8, Kg + baseK + (size_t)row * ldq + c8);
            cp16(Vb + row * FQSTR + c8, Vg + baseK + (size_t)row * ldq + c8);
        }
        if (t < 16) cp16(mksm + s * 64 + t * 4, mask + b * SS + kt * 64 + t * 4);
    };

    // group0: kv0 + Q; group1: kv1
    load_kv(0, 0);
    #pragma unroll
    for (int i = 0; i < 4; i++) {
        int id = t + i * 256;
        int row = id >> 3, c8 = (id & 7) << 3;
        cp16(smh + row * FQSTR + c8, Q + baseQ + (size_t)row * ldq + c8);
    }
    cp_commit();
    load_kv(1, 1);
    cp_commit();

    cp_wait<1>();
    __syncthreads();

    int arow_l = lane & 15;
    int acol_l = (lane >> 4) << 3;
    int mat = lane >> 3, lr = lane & 7;
    uint32_t qf[4][4];
    int qb = wid * 16;
    #pragma unroll
    for (int ks = 0; ks < 4; ks++)
        ldm_x4(qf[ks], sbase +
            ((uint32_t)((qb + arow_l) * FQSTR + ks * 16 + acol_l) << 1));

    float m0 = -1e30f, m1 = -1e30f, l0 = 0.f, l1 = 0.f;
    float acc[8][4];
    #pragma unroll
    for (int nt = 0; nt < 8; nt++)
        #pragma unroll
        for (int i = 0; i < 4; i++) acc[nt][i] = 0.f;

    for (int kt = 0; kt < SS / 64; kt++) {
        cp_wait<1>();
        __syncthreads();

        // issue kv(kt+2) into stage consumed last iteration
        int nx = kt + 2;
        if (nx < SS / 64) load_kv(nx, nx % 3);
        cp_commit();

        int st = kt % 3;
        uint32_t Ku = sbase + (uint32_t)((KOFF + st * FKV_H) * 2);
        uint32_t Vu = sbase + (uint32_t)((VOFF + st * FKV_H) * 2);
        const int* mk = mksm + st * 64;

        float sf[8][4];
        #pragma unroll
        for (int nt = 0; nt < 8; nt++)
            #pragma unroll
            for (int i = 0; i < 4; i++) sf[nt][i] = 0.f;

        #pragma unroll
        for (int ks = 0; ks < 4; ks++) {
            int kk = ks * 16 + ((mat & 1) << 3);
            #pragma unroll
            for (int p = 0; p < 4; p++) {
                int kn = p * 16 + ((mat >> 1) << 3) + lr;
                uint32_t kb[4];
                ldm_x4(kb, Ku + ((uint32_t)(kn * FQSTR + kk) << 1));
                mma16(sf[2 * p],     qf[ks], kb);
                mma16(sf[2 * p + 1], qf[ks], kb + 2);
            }
        }

        float mx0 = -1e30f, mx1 = -1e30f;
        #pragma unroll
        for (int nt = 0; nt < 8; nt++) {
            float bia0 = mk[nt * 8 + 2 * c]     ? 0.f : -1e9f;
            float bia1 = mk[nt * 8 + 2 * c + 1] ? 0.f : -1e9f;
            sf[nt][0] = sf[nt][0] * 0.125f + bia0;
            sf[nt][1] = sf[nt][1] * 0.125f + bia1;
            sf[nt][2] = sf[nt][2] * 0.125f + bia0;
            sf[nt][3] = sf[nt][3] * 0.125f + bia1;
            mx0 = fmaxf(mx0, fmaxf(sf[nt][0], sf[nt][1]));
            mx1 = fmaxf(mx1, fmaxf(sf[nt][2], sf[nt][3]));
        }
        mx0 = fmaxf(mx0, __shfl_xor_sync(0xffffffffu, mx0, 1));
        mx0 = fmaxf(mx0, __shfl_xor_sync(0xffffffffu, mx0, 2));
        mx1 = fmaxf(mx1, __shfl_xor_sync(0xffffffffu, mx1, 1));
        mx1 = fmaxf(mx1, __shfl_xor_sync(0xffffffffu, mx1, 2));

        float mn0 = fmaxf(m0, mx0), mn1 = fmaxf(m1, mx1);
        float al0 = __expf(m0 - mn0), al1 = __expf(m1 - mn1);
        m0 = mn0; m1 = mn1;

        float ps0 = 0.f, ps1 = 0.f;
        #pragma unroll
        for (int nt = 0; nt < 8; nt++) {
            sf[nt][0] = __expf(sf[nt][0] - mn0);
            sf[nt][1] = __expf(sf[nt][1] - mn0);
            sf[nt][2] = __expf(sf[nt][2] - mn1);
            sf[nt][3] = __expf(sf[nt][3] - mn1);
            ps0 += sf[nt][0] + sf[nt][1];
            ps1 += sf[nt][2] + sf[nt][3];
        }
        ps0 += __shfl_xor_sync(0xffffffffu, ps0, 1);
        ps0 += __shfl_xor_sync(0xffffffffu, ps0, 2);
        ps1 += __shfl_xor_sync(0xffffffffu, ps1, 1);
        ps1 += __shfl_xor_sync(0xffffffffu, ps1, 2);
        l0 = l0 * al0 + ps0;
        l1 = l1 * al1 + ps1;

        #pragma unroll
        for (int nt = 0; nt < 8; nt++) {
            acc[nt][0] *= al0; acc[nt][1] *= al0;
            acc[nt][2] *= al1; acc[nt][3] *= al1;
        }

        #pragma unroll
        for (int ks = 0; ks < 4; ks++) {
            uint32_t af[4];
            af[0] = packh2(sf[2 * ks][0],     sf[2 * ks][1]);
            af[1] = packh2(sf[2 * ks][2],     sf[2 * ks][3]);
            af[2] = packh2(sf[2 * ks + 1][0], sf[2 * ks + 1][1]);
            af[3] = packh2(sf[2 * ks + 1][2], sf[2 * ks + 1][3]);
            int vk = ks * 16 + ((mat & 1) << 3) + lr;
            #pragma unroll
            for (int p = 0; p < 4; p++) {
                int vn = p * 16 + ((mat >> 1) << 3);
                uint32_t vb[4];
                ldm_x4t(vb, Vu + ((uint32_t)(vk * FQSTR + vn) << 1));
                mma16(acc[2 * p],     af, vb);
                mma16(acc[2 * p + 1], af, vb + 2);
            }
        }
    }

    float inv0 = 1.f / l0, inv1 = 1.f / l1;
    size_t r0 = ((size_t)(b * SS + q0 + qb + g)) * DD + h * DHD;
    size_t r1 = r0 + 8 * DD;
    #pragma unroll
    for (int nt = 0; nt < 8; nt++) {
        int col = nt * 8 + 2 * c;
        *(__half2*)(O + r0 + col) =
            __floats2half2_rn(acc[nt][0] * inv0, acc[nt][1] * inv0);
        *(__half2*)(O + r1 + col) =
            __floats2half2_rn(acc[nt][2] * inv1, acc[nt][3] * inv1);
    }
}

// ---------------- launch ---------------------------------------------------
extern "C" void kernel_launch(void* const* d_in, const int* in_sizes, int n_in,
                              void* d_out, int out_size)
{
    const float* hidden = (const float*)d_in[0];
    const int*   mask   = (const int*)d_in[1];
    const float* wq = (const float*)d_in[2];
    const float* bq = (const float*)d_in[3];
    const float* wk = (const float*)d_in[4];
    const float* bk = (const float*)d_in[5];
    const float* wv = (const float*)d_in[6];
    const float* bv = (const float*)d_in[7];
    const float* wo = (const float*)d_in[8];
    const float* bo = (const float*)d_in[9];
    const float* w1 = (const float*)d_in[10];
    const float* b1 = (const float*)d_in[11];
    const float* w2 = (const float*)d_in[12];
    const float* b2 = (const float*)d_in[13];
    const float* ln1_g = (const float*)d_in[14];
    const float* ln1_b = (const float*)d_in[15];
    const float* ln2_g = (const float*)d_in[16];
    const float* ln2_b = (const float*)d_in[17];
    float* out = (float*)d_out;

    __half *ln, *qkv, *attn, *f1, *wqkvh, *woh, *w1h, *w2h;
    float *h1, *bqkv;
    cudaGetSymbolAddress((void**)&ln,    g_ln);
    cudaGetSymbolAddress((void**)&qkv,   g_qkv);
    cudaGetSymbolAddress((void**)&attn,  g_attn);
    cudaGetSymbolAddress((void**)&h1,    g_h1);
    cudaGetSymbolAddress((void**)&f1,    g_f1);
    cudaGetSymbolAddress((void**)&wqkvh, g_wqkv);
    cudaGetSymbolAddress((void**)&bqkv,  g_bqkv);
    cudaGetSymbolAddress((void**)&woh,   g_wo);
    cudaGetSymbolAddress((void**)&w1h,   g_w1);
    cudaGetSymbolAddress((void**)&w2h,   g_w2);

    cudaFuncSetAttribute(flash_f16,
                         cudaFuncAttributeMaxDynamicSharedMemorySize, FLASH_SMEM);
    cudaFuncSetAttribute(gemm_f16<1>,
                         cudaFuncAttributeMaxDynamicSharedMemorySize, GEMM_SMEM);
    cudaFuncSetAttribute(gemm_f16<2>,
                         cudaFuncAttributeMaxDynamicSharedMemorySize, GEMM_SMEM);
    cudaFuncSetAttribute(gemm_f16<3>,
                         cudaFuncAttributeMaxDynamicSharedMemorySize, GEMM_SMEM);

    // one fused pack launch (weights -> fp16, biases -> fused buffer)
    pack_all<<<(unsigned)PACK_BLOCKS, 256>>>(wq, wk, wv, wo, w1, w2, bq, bk, bv,
                                             wqkvh, woh, w1h, w2h, bqkv);

    // 1) LN1
    ln_kernel<<<NROWS, 256>>>(hidden, ln1_g, ln1_b, ln);

    // 2) fused QKV projection -> fp16
    dim3 gQKV(NQKV / 128, NROWS / 128);
    gemm_f16<3><<<gQKV, 256, GEMM_SMEM>>>(ln, wqkvh, bqkv, nullptr, qkv,
                                          NROWS, DD, NQKV);

    // 3) attention (fp16 tensor flash) -> fp16
    flash_f16<<<dim3(SS / 128, HH, BB), 256, FLASH_SMEM>>>(
        qkv, qkv + DD, qkv + 2 * DD, NQKV, mask, attn);

    // 4) output projection + residual -> fp32
    dim3 gD(DD / 128, NROWS / 128);
    gemm_f16<2><<<gD, 256, GEMM_SMEM>>>(attn, woh, bo, hidden, h1, NROWS, DD, DD);

    // 5) LN2
    ln_kernel<<<NROWS, 256>>>(h1, ln2_g, ln2_b, ln);

    // 6) FFN
    dim3 gF(DFF / 128, NROWS / 128);
    gemm_f16<1><<<gF, 256, GEMM_SMEM>>>(ln, w1h, b1, nullptr, f1, NROWS, DD, DFF);
    gemm_f16<2><<<gD, 256, GEMM_SMEM>>>(f1, w2h, b2, h1, out, NROWS, DFF, DD);
}